// round 7
// baseline (speedup 1.0000x reference)
#include <cuda_runtime.h>
#include <cuda_bf16.h>
#include <math.h>

#define BB 4
#define CC 192
#define C2 384
#define HWN 16384
#define HIMG 128
#define CHD 48
#define HIDC 510
#define HID2 1020
#define GGPAD 512
#define EPSLN 1e-5f

__device__ __forceinline__ unsigned smem_u32(const void* p) {
    unsigned a;
    asm("{ .reg .u64 t; cvta.to.shared.u64 t, %1; cvt.u32.u64 %0, t; }"
        : "=r"(a) : "l"(p));
    return a;
}
#define CP_ASYNC16(dst, src) \
    asm volatile("cp.async.cg.shared.global [%0], [%1], 16;" :: "r"(dst), "l"(src))
#define CP_COMMIT() asm volatile("cp.async.commit_group;" ::: "memory")
#define CP_WAIT(n)  asm volatile("cp.async.wait_group %0;" :: "n"(n) : "memory")

__device__ __forceinline__ void ldm_x4(unsigned& r0, unsigned& r1, unsigned& r2, unsigned& r3,
                                       unsigned addr) {
    asm volatile("ldmatrix.sync.aligned.m8n8.x4.shared.b16 {%0,%1,%2,%3}, [%4];"
        : "=r"(r0), "=r"(r1), "=r"(r2), "=r"(r3) : "r"(addr));
}
__device__ __forceinline__ void ldm_x4_t(unsigned& r0, unsigned& r1, unsigned& r2, unsigned& r3,
                                         unsigned addr) {
    asm volatile("ldmatrix.sync.aligned.m8n8.x4.trans.shared.b16 {%0,%1,%2,%3}, [%4];"
        : "=r"(r0), "=r"(r1), "=r"(r2), "=r"(r3) : "r"(addr));
}
__device__ __forceinline__ void mma_bf(float* d, const unsigned* a, unsigned b0, unsigned b1) {
    asm volatile("mma.sync.aligned.m16n8k16.row.col.f32.bf16.bf16.f32 "
        "{%0,%1,%2,%3}, {%4,%5,%6,%7}, {%8,%9}, {%0,%1,%2,%3};"
        : "+f"(d[0]), "+f"(d[1]), "+f"(d[2]), "+f"(d[3])
        : "r"(a[0]), "r"(a[1]), "r"(a[2]), "r"(a[3]), "r"(b0), "r"(b1));
}

// ---------------- scratch ----------------
__device__ float g_qpre [BB*C2*HWN];
__device__ float g_kv1pre[BB*C2*HWN];
__device__ float g_kv2pre[BB*C2*HWN];
__device__ float g_q   [BB*C2*HWN];
__device__ float g_kv1 [BB*C2*HWN];
__device__ float g_kv2 [BB*C2*HWN];
__device__ float g_x2  [BB*CC*HWN];
__device__ float g_h   [BB*HID2*HWN];
__device__ float g_S   [32*CHD*CHD];
__device__ float g_nrm [32*2*CHD];

// bf16 hi/lo activations, natural layout: [b][channel][pixel]
__device__ __align__(16) unsigned short xt_a_hi [BB*CC*HWN];
__device__ __align__(16) unsigned short xt_a_lo [BB*CC*HWN];
__device__ __align__(16) unsigned short xt_k1_hi[BB*CC*HWN];
__device__ __align__(16) unsigned short xt_k1_lo[BB*CC*HWN];
__device__ __align__(16) unsigned short xt_k2_hi[BB*CC*HWN];
__device__ __align__(16) unsigned short xt_k2_lo[BB*CC*HWN];
__device__ __align__(16) unsigned short xt_ao_hi[BB*C2*HWN];
__device__ __align__(16) unsigned short xt_ao_lo[BB*C2*HWN];
__device__ __align__(16) unsigned short xt_gg_hi[BB*GGPAD*HWN];
__device__ __align__(16) unsigned short xt_gg_lo[BB*GGPAD*HWN];
// converted weights (row-major [O][Cpad])
#define OFF_Q   0
#define OFF_K1  (384*192)
#define OFF_K2  (2*384*192)
#define OFF_P   (3*384*192)
#define OFF_PIN (3*384*192 + 192*384)
#define OFF_PO  (3*384*192 + 192*384 + 1020*192)
#define WTOT    (3*384*192 + 192*384 + 1020*192 + 192*512)
#define WPAD    (64*512)
__device__ __align__(16) unsigned short g_whi[WTOT + WPAD];
__device__ __align__(16) unsigned short g_wlo[WTOT + WPAD];

// ---------------- fp32 -> bf16 hi/lo helpers ----------------
__device__ __forceinline__ void cvt2(float a, float b, unsigned& h, unsigned& l) {
    __nv_bfloat16 ha = __float2bfloat16_rn(a), hb = __float2bfloat16_rn(b);
    h = (unsigned)__bfloat16_as_ushort(ha) | ((unsigned)__bfloat16_as_ushort(hb) << 16);
    __nv_bfloat16 la = __float2bfloat16_rn(a - __bfloat162float(ha));
    __nv_bfloat16 lb = __float2bfloat16_rn(b - __bfloat162float(hb));
    l = (unsigned)__bfloat16_as_ushort(la) | ((unsigned)__bfloat16_as_ushort(lb) << 16);
}
__device__ __forceinline__ void cvt8(const float* v, uint4& hv, uint4& lv) {
    unsigned h[4], l[4];
    #pragma unroll
    for (int i = 0; i < 4; i++) cvt2(v[2*i], v[2*i+1], h[i], l[i]);
    hv = make_uint4(h[0], h[1], h[2], h[3]);
    lv = make_uint4(l[0], l[1], l[2], l[3]);
}

// ---------------- merged weight conversion (1 launch) ----------------
__global__ void wconv_all(const float* __restrict__ q_w, const float* __restrict__ kv1_w,
                          const float* __restrict__ kv2_w, const float* __restrict__ proj_w,
                          const float* __restrict__ pin_w, const float* __restrict__ pout_w) {
    int r = blockIdx.x;
    const float* W; int o, Cin, Cpad, off;
    if (r < 384)        { W = q_w;    o = r;        Cin = 192; Cpad = 192; off = OFF_Q; }
    else if (r < 768)   { W = kv1_w;  o = r - 384;  Cin = 192; Cpad = 192; off = OFF_K1; }
    else if (r < 1152)  { W = kv2_w;  o = r - 768;  Cin = 192; Cpad = 192; off = OFF_K2; }
    else if (r < 1344)  { W = proj_w; o = r - 1152; Cin = 384; Cpad = 384; off = OFF_P; }
    else if (r < 2364)  { W = pin_w;  o = r - 1344; Cin = 192; Cpad = 192; off = OFF_PIN; }
    else                { W = pout_w; o = r - 2364; Cin = 510; Cpad = 512; off = OFF_PO; }
    int c0 = threadIdx.x * 8;
    if (c0 >= Cpad) return;
    float v[8];
    #pragma unroll
    for (int j = 0; j < 8; j++) {
        int c = c0 + j;
        v[j] = (c < Cin) ? W[(size_t)o * Cin + c] : 0.f;
    }
    uint4 hv, lv; cvt8(v, hv, lv);
    *(uint4*)(g_whi + (size_t)off + (size_t)o * Cpad + c0) = hv;
    *(uint4*)(g_wlo + (size_t)off + (size_t)o * Cpad + c0) = lv;
}

// ======================= HMMA GEMM body =====================================
#define BK 32
#define ASTRIDE 40
#define PSTR 72
#define A_BYTES (128 * ASTRIDE * 2)
#define B_BYTES (BK * PSTR * 2)
#define BUF_BYTES (2 * A_BYTES + 2 * B_BYTES)
#define GEMM_SMEM (2 * BUF_BYTES)
#define YSTRIDE 68

template<bool RESID>
__device__ __forceinline__
void gemm_body(const unsigned short* __restrict__ Whi, const unsigned short* __restrict__ Wlo,
               const unsigned short* __restrict__ XhiB, const unsigned short* __restrict__ XloB,
               const float* __restrict__ R, float* __restrict__ Y, int O, int Cpad,
               int b, int p0, int o0, char* dsm) {
    unsigned sbase = smem_u32(dsm);
    int t = threadIdx.x, wid = t >> 5, lane = t & 31;
    int warpM = (wid >> 1) * 32;
    int warpN = (wid & 1) * 32;

    const unsigned short* WhiB = Whi + (size_t)o0 * Cpad;
    const unsigned short* WloB = Wlo + (size_t)o0 * Cpad;

    int nk = Cpad / BK;

    auto fill = [&](int kt) {
        int buf = kt & 1;
        unsigned bb = sbase + buf * BUF_BYTES;
        int k0 = kt * BK;
        #pragma unroll
        for (int j = 0; j < 6; j++) {
            int ci = j * 256 + t;
            if (ci < 1024) {
                int m = ci & 511;
                int row = m >> 2, g = m & 3;
                const unsigned short* src = ((ci < 512) ? WhiB : WloB)
                                            + (size_t)row * Cpad + k0 + g * 8;
                unsigned dst = bb + ((ci < 512) ? 0u : A_BYTES)
                             + (unsigned)(row * ASTRIDE + g * 8) * 2;
                CP_ASYNC16(dst, src);
            } else {
                int m = ci - 1024;
                int mm = m & 255;
                int row = mm >> 3, g = mm & 7;
                const unsigned short* src = ((m < 256) ? XhiB : XloB)
                                            + (size_t)(k0 + row) * HWN + g * 8;
                unsigned dst = bb + 2 * A_BYTES + ((m < 256) ? 0u : B_BYTES)
                             + (unsigned)(row * PSTR + g * 8) * 2;
                CP_ASYNC16(dst, src);
            }
        }
        CP_COMMIT();
    };

    float acc[2][4][4];
    #pragma unroll
    for (int i = 0; i < 2; i++)
        #pragma unroll
        for (int j = 0; j < 4; j++)
            #pragma unroll
            for (int k = 0; k < 4; k++) acc[i][j][k] = 0.f;

    fill(0);

    int rsel = lane & 15, csel = (lane >> 4) * 8;
    int bkr = (lane & 7) + ((lane >> 4) & 1) * 8;
    int bpc = ((lane >> 3) & 1) * 8;

    for (int kt = 0; kt < nk; kt++) {
        if (kt + 1 < nk) { fill(kt + 1); CP_WAIT(1); }
        else             { CP_WAIT(0); }
        __syncthreads();

        unsigned bb = sbase + (kt & 1) * BUF_BYTES;
        unsigned Ah = bb, Al = bb + A_BYTES;
        unsigned Bh = bb + 2 * A_BYTES, Bl = Bh + B_BYTES;

        #pragma unroll
        for (int kk = 0; kk < 2; kk++) {
            int kc = csel + kk * 16;
            unsigned ah[2][4], al[2][4], bh[2][4], bl[2][4];
            #pragma unroll
            for (int mt = 0; mt < 2; mt++) {
                unsigned off = (unsigned)((warpM + mt * 16 + rsel) * ASTRIDE + kc) * 2;
                ldm_x4(ah[mt][0], ah[mt][1], ah[mt][2], ah[mt][3], Ah + off);
                ldm_x4(al[mt][0], al[mt][1], al[mt][2], al[mt][3], Al + off);
            }
            #pragma unroll
            for (int np = 0; np < 2; np++) {
                unsigned off = (unsigned)((kk * 16 + bkr) * PSTR + warpN + np * 16 + bpc) * 2;
                ldm_x4_t(bh[np][0], bh[np][1], bh[np][2], bh[np][3], Bh + off);
                ldm_x4_t(bl[np][0], bl[np][1], bl[np][2], bl[np][3], Bl + off);
            }
            #pragma unroll
            for (int mt = 0; mt < 2; mt++)
                #pragma unroll
                for (int nt = 0; nt < 4; nt++) {
                    int np = nt >> 1, hf = nt & 1;
                    mma_bf(acc[mt][nt], ah[mt], bh[np][hf], bh[np][hf + 2]);
                    mma_bf(acc[mt][nt], ah[mt], bl[np][hf], bl[np][hf + 2]);
                    mma_bf(acc[mt][nt], al[mt], bh[np][hf], bh[np][hf + 2]);
                }
        }
        __syncthreads();
    }

    float* Ysm = (float*)dsm;
    #pragma unroll
    for (int mt = 0; mt < 2; mt++)
        #pragma unroll
        for (int nt = 0; nt < 4; nt++) {
            int r0 = warpM + mt * 16 + (lane >> 2);
            int cc = warpN + nt * 8 + (lane & 3) * 2;
            Ysm[r0 * YSTRIDE + cc]           = acc[mt][nt][0];
            Ysm[r0 * YSTRIDE + cc + 1]       = acc[mt][nt][1];
            Ysm[(r0 + 8) * YSTRIDE + cc]     = acc[mt][nt][2];
            Ysm[(r0 + 8) * YSTRIDE + cc + 1] = acc[mt][nt][3];
        }
    __syncthreads();
    #pragma unroll
    for (int i = 0; i < 8; i++) {
        int idx = i * 256 + t;
        int row = idx >> 4, c4 = (idx & 15) * 4;
        int o = o0 + row;
        if (o < O) {
            float4 v = *(float4*)(Ysm + row * YSTRIDE + c4);
            size_t goff = ((size_t)b * O + o) * HWN + p0 + c4;
            if (RESID) {
                float4 q = *(const float4*)(R + goff);
                v.x += q.x; v.y += q.y; v.z += q.z; v.w += q.w;
            }
            *(float4*)(Y + goff) = v;
        }
    }
}

template<bool RESID>
__global__ __launch_bounds__(256)
void gemm_mma(const unsigned short* __restrict__ Whi, const unsigned short* __restrict__ Wlo,
              const unsigned short* __restrict__ Xhi, const unsigned short* __restrict__ Xlo,
              const float* __restrict__ R, float* __restrict__ Y, int O, int Cpad) {
    extern __shared__ char dsm[];
    int b = blockIdx.z;
    gemm_body<RESID>(Whi, Wlo,
                     Xhi + (size_t)b * Cpad * HWN + blockIdx.x * 64,
                     Xlo + (size_t)b * Cpad * HWN + blockIdx.x * 64,
                     R, Y, O, Cpad, b, blockIdx.x * 64, blockIdx.y * 128, dsm);
}

// merged q/kv1/kv2 GEMM: grid (256, 3, 12); z: which = z>>2, b = z&3
__global__ __launch_bounds__(256)
void gemm3(void) {
    extern __shared__ char dsm[];
    int z = blockIdx.z, which = z >> 2, b = z & 3;
    const unsigned short *Whi, *Wlo, *Xhi, *Xlo;
    float* Y;
    if (which == 0)      { Whi = g_whi + OFF_Q;  Wlo = g_wlo + OFF_Q;  Xhi = xt_a_hi;  Xlo = xt_a_lo;  Y = g_qpre; }
    else if (which == 1) { Whi = g_whi + OFF_K1; Wlo = g_wlo + OFF_K1; Xhi = xt_k1_hi; Xlo = xt_k1_lo; Y = g_kv1pre; }
    else                 { Whi = g_whi + OFF_K2; Wlo = g_wlo + OFF_K2; Xhi = xt_k2_hi; Xlo = xt_k2_lo; Y = g_kv2pre; }
    gemm_body<false>(Whi, Wlo,
                     Xhi + (size_t)b * CC * HWN + blockIdx.x * 64,
                     Xlo + (size_t)b * CC * HWN + blockIdx.x * 64,
                     nullptr, Y, C2, CC, b, blockIdx.x * 64, blockIdx.y * 128, dsm);
}

// ---------------- LayerNorm -> bf16 hi/lo [c][p], 4 px/thread ---------------
__global__ void ln_cp(const float* __restrict__ X, const float* __restrict__ w,
                      const float* __restrict__ bia,
                      unsigned short* __restrict__ Hi, unsigned short* __restrict__ Lo) {
    int b = blockIdx.y;
    int p = (blockIdx.x * 256 + threadIdx.x) * 4;
    const float* xp = X + (size_t)b * CC * HWN + p;
    float4 s = make_float4(0,0,0,0), q = make_float4(0,0,0,0);
    #pragma unroll 4
    for (int c = 0; c < CC; c++) {
        float4 v = *(const float4*)(xp + (size_t)c * HWN);
        s.x += v.x; s.y += v.y; s.z += v.z; s.w += v.w;
        q.x += v.x*v.x; q.y += v.y*v.y; q.z += v.z*v.z; q.w += v.w*v.w;
    }
    const float invc = 1.f / CC;
    float4 mu = make_float4(s.x*invc, s.y*invc, s.z*invc, s.w*invc);
    float4 iv;
    iv.x = rsqrtf(fmaxf(q.x*invc - mu.x*mu.x, 0.f) + EPSLN);
    iv.y = rsqrtf(fmaxf(q.y*invc - mu.y*mu.y, 0.f) + EPSLN);
    iv.z = rsqrtf(fmaxf(q.z*invc - mu.z*mu.z, 0.f) + EPSLN);
    iv.w = rsqrtf(fmaxf(q.w*invc - mu.w*mu.w, 0.f) + EPSLN);
    size_t base = (size_t)b * CC * HWN + p;
    #pragma unroll 4
    for (int c = 0; c < CC; c++) {
        float4 v = *(const float4*)(xp + (size_t)c * HWN);
        float wc = w[c], bc = bia[c];
        float o0 = (v.x - mu.x) * iv.x * wc + bc;
        float o1 = (v.y - mu.y) * iv.y * wc + bc;
        float o2 = (v.z - mu.z) * iv.z * wc + bc;
        float o3 = (v.w - mu.w) * iv.w * wc + bc;
        unsigned h0, l0, h1, l1;
        cvt2(o0, o1, h0, l0);
        cvt2(o2, o3, h1, l1);
        *(uint2*)(Hi + base + (size_t)c * HWN) = make_uint2(h0, h1);
        *(uint2*)(Lo + base + (size_t)c * HWN) = make_uint2(l0, l1);
    }
}

// ---------------- depthwise 3x3 core ----------------
__device__ __forceinline__ void dw_core(const float* __restrict__ xp, const float* kv,
                                        int h, int wcol, float& a0, float& a1,
                                        float& a2, float& a3) {
    #pragma unroll
    for (int dy = -1; dy <= 1; dy++) {
        int hh = h + dy;
        if (hh < 0 || hh >= HIMG) continue;
        const float* r = xp + hh * HIMG + wcol;
        float4 m = *(const float4*)r;
        float lf = (wcol > 0) ? r[-1] : 0.f;
        float rt = (wcol < 124) ? r[4] : 0.f;
        const float* k = kv + (dy + 1) * 3;
        a0 += k[0]*lf  + k[1]*m.x + k[2]*m.y;
        a1 += k[0]*m.x + k[1]*m.y + k[2]*m.z;
        a2 += k[0]*m.y + k[1]*m.z + k[2]*m.w;
        a3 += k[0]*m.z + k[1]*m.w + k[2]*rt;
    }
}

// merged kv1+kv2 depthwise (grid.y = 768)
__global__ void dwconv_kv(const float* __restrict__ Wt1, const float* __restrict__ Wt2) {
    int b = blockIdx.z, cc = blockIdx.y;
    int p = (blockIdx.x * 256 + threadIdx.x) * 4;
    int h = p >> 7, wcol = p & 127;
    const float* X; const float* Wt; float* Y; int c;
    if (cc < C2) { X = g_kv1pre; Wt = Wt1; Y = g_kv1; c = cc; }
    else         { X = g_kv2pre; Wt = Wt2; Y = g_kv2; c = cc - C2; }
    const float* xp = X + ((size_t)b * C2 + c) * HWN;
    float kv[9];
    #pragma unroll
    for (int i = 0; i < 9; i++) kv[i] = Wt[(size_t)c * 9 + i];
    float a0 = 0, a1 = 0, a2 = 0, a3 = 0;
    dw_core(xp, kv, h, wcol, a0, a1, a2, a3);
    *(float4*)(Y + ((size_t)b * C2 + c) * HWN + p) = make_float4(a0, a1, a2, a3);
}

__global__ void dwconv_g2(const float* __restrict__ X, const float* __restrict__ Wt,
                          float* __restrict__ Y) {
    int b = blockIdx.z, o = blockIdx.y;
    int p = (blockIdx.x * 256 + threadIdx.x) * 4;
    int h = p >> 7, wcol = p & 127;
    int i0 = (o >> 1) << 1;
    const float* x0 = X + ((size_t)b * C2 + i0) * HWN;
    float kv[18];
    #pragma unroll
    for (int i = 0; i < 18; i++) kv[i] = Wt[(size_t)o * 18 + i];
    float a0 = 0, a1 = 0, a2 = 0, a3 = 0;
    dw_core(x0, kv, h, wcol, a0, a1, a2, a3);
    dw_core(x0 + HWN, kv + 9, h, wcol, a0, a1, a2, a3);
    *(float4*)(Y + ((size_t)b * C2 + o) * HWN + p) = make_float4(a0, a1, a2, a3);
}

// ---------------- fused FFN dwconv + gated gelu -> bf16 [c][p] --------------
__global__ void dwgelu(const float* __restrict__ X, const float* __restrict__ Wt,
                       unsigned short* __restrict__ Hi, unsigned short* __restrict__ Lo) {
    int b = blockIdx.z, c = blockIdx.y;
    int p = (blockIdx.x * 256 + threadIdx.x) * 4;
    size_t oidx = ((size_t)b * GGPAD + c) * HWN + p;
    if (c >= HIDC) {
        *(uint2*)(Hi + oidx) = make_uint2(0, 0);
        *(uint2*)(Lo + oidx) = make_uint2(0, 0);
        return;
    }
    int h = p >> 7, wcol = p & 127;
    float va[8];
    #pragma unroll
    for (int half = 0; half < 2; half++) {
        int ch = c + half * HIDC;
        const float* xp = X + ((size_t)b * HID2 + ch) * HWN;
        float kv[9];
        #pragma unroll
        for (int i = 0; i < 9; i++) kv[i] = Wt[(size_t)ch * 9 + i];
        float a0 = 0, a1 = 0, a2 = 0, a3 = 0;
        dw_core(xp, kv, h, wcol, a0, a1, a2, a3);
        va[half*4+0] = a0; va[half*4+1] = a1; va[half*4+2] = a2; va[half*4+3] = a3;
    }
    float o[4];
    #pragma unroll
    for (int j = 0; j < 4; j++) {
        float a = va[j];
        float ge = 0.5f * a * (1.f + erff(a * 0.70710678118654752f));
        o[j] = ge * va[4+j];
    }
    unsigned h0, l0, h1, l1;
    cvt2(o[0], o[1], h0, l0);
    cvt2(o[2], o[3], h1, l1);
    *(uint2*)(Hi + oidx) = make_uint2(h0, h1);
    *(uint2*)(Lo + oidx) = make_uint2(l0, l1);
}

// ---------------- attention ----------------
__global__ void zero_attn() {
    int i = blockIdx.x * 256 + threadIdx.x;
    if (i < 32 * CHD * CHD) g_S[i] = 0.f;
    if (i < 32 * 96) g_nrm[i] = 0.f;
}

__global__ void skernel() {
    int m = blockIdx.x, ns = blockIdx.y;
    int b = m >> 3, br = (m >> 2) & 1, hh = m & 3;
    const float* qb = g_q + ((size_t)b * C2 + br * CC + hh * CHD) * HWN;
    const float* kb = (br ? g_kv2 : g_kv1) + ((size_t)b * C2 + hh * CHD) * HWN;
    __shared__ float Qs[CHD][65];
    __shared__ float Ks[CHD][65];
    int t = threadIdx.x;
    int tx = t & 15, ty = t >> 4;
    float acc[3][3];
    #pragma unroll
    for (int i = 0; i < 3; i++)
        #pragma unroll
        for (int j = 0; j < 3; j++) acc[i][j] = 0.f;
    const float* nrow = (t < CHD) ? &Qs[t][0] : ((t < 96) ? &Ks[t - CHD][0] : (const float*)0);
    float nacc = 0.f;
    int nbeg = ns * 1024;
    for (int n0 = nbeg; n0 < nbeg + 1024; n0 += 64) {
        #pragma unroll
        for (int i = t; i < CHD * 64; i += 256) {
            int rr = i >> 6, cc = i & 63;
            Qs[rr][cc] = qb[(size_t)rr * HWN + n0 + cc];
            Ks[rr][cc] = kb[(size_t)rr * HWN + n0 + cc];
        }
        __syncthreads();
        if (nrow) {
            #pragma unroll 8
            for (int cc = 0; cc < 64; cc++) { float v = nrow[cc]; nacc += v * v; }
        }
        #pragma unroll 8
        for (int kk = 0; kk < 64; kk++) {
            float qv[3], kvv[3];
            #pragma unroll
            for (int i = 0; i < 3; i++) qv[i] = Qs[ty + 16 * i][kk];
            #pragma unroll
            for (int j = 0; j < 3; j++) kvv[j] = Ks[tx + 16 * j][kk];
            #pragma unroll
            for (int i = 0; i < 3; i++)
                #pragma unroll
                for (int j = 0; j < 3; j++) acc[i][j] += qv[i] * kvv[j];
        }
        __syncthreads();
    }
    #pragma unroll
    for (int i = 0; i < 3; i++)
        #pragma unroll
        for (int j = 0; j < 3; j++)
            atomicAdd(&g_S[m * CHD * CHD + (ty + 16 * i) * CHD + (tx + 16 * j)], acc[i][j]);
    if (t < 96) atomicAdd(&g_nrm[m * 96 + t], nacc);
}

__global__ void softmax_kernel(const float* __restrict__ t1, const float* __restrict__ t2) {
    int m = blockIdx.x;
    int c = threadIdx.x;
    __shared__ float nk[CHD];
    if (c < CHD) nk[c] = fmaxf(sqrtf(g_nrm[m * 96 + CHD + c]), 1e-12f);
    __syncthreads();
    if (c >= CHD) return;
    int br = (m >> 2) & 1, hh = m & 3;
    float tmp = (br ? t2 : t1)[hh];
    float nq = fmaxf(sqrtf(g_nrm[m * 96 + c]), 1e-12f);
    float* row = g_S + (size_t)m * CHD * CHD + c * CHD;
    float vals[CHD];
    float mx = -1e30f;
    #pragma unroll
    for (int d = 0; d < CHD; d++) {
        float v = row[d] / (nq * nk[d]) * tmp;
        vals[d] = v;
        mx = fmaxf(mx, v);
    }
    float sum = 0.f;
    #pragma unroll
    for (int d = 0; d < CHD; d++) { vals[d] = __expf(vals[d] - mx); sum += vals[d]; }
    float inv = 1.f / sum;
    #pragma unroll
    for (int d = 0; d < CHD; d++) row[d] = vals[d] * inv;
}

__global__ void av_cp() {
    int m = blockIdx.x;
    int b = m >> 3, br = (m >> 2) & 1, hh = m & 3;
    __shared__ float As[CHD * CHD];
    for (int i = threadIdx.x; i < CHD * CHD; i += 128) As[i] = g_S[(size_t)m * CHD * CHD + i];
    __syncthreads();
    const float* vb = (br ? g_kv2 : g_kv1) + ((size_t)b * C2 + CC + hh * CHD) * HWN;
    int p = blockIdx.y * 256 + threadIdx.x * 2;
    float acc0[CHD], acc1[CHD];
    #pragma unroll
    for (int c = 0; c < CHD; c++) { acc0[c] = 0.f; acc1[c] = 0.f; }
    for (int d = 0; d < CHD; d++) {
        float2 v = *(const float2*)(vb + (size_t)d * HWN + p);
        #pragma unroll
        for (int c = 0; c < CHD; c++) {
            float a = As[c * CHD + d];
            acc0[c] += a * v.x;
            acc1[c] += a * v.y;
        }
    }
    int off = br * CC + hh * CHD;
    size_t base = ((size_t)b * C2 + off) * HWN + p;
    #pragma unroll
    for (int c = 0; c < CHD; c++) {
        unsigned h, l; cvt2(acc0[c], acc1[c], h, l);
        *(unsigned*)(xt_ao_hi + base + (size_t)c * HWN) = h;
        *(unsigned*)(xt_ao_lo + base + (size_t)c * HWN) = l;
    }
}

// ---------------- launch ----------------
extern "C" void kernel_launch(void* const* d_in, const int* in_sizes, int n_in,
                              void* d_out, int out_size) {
    const float* x       = (const float*)d_in[0];
    const float* kv1in   = (const float*)d_in[1];
    const float* kv2in   = (const float*)d_in[2];
    const float* n1w = (const float*)d_in[3];  const float* n1b = (const float*)d_in[4];
    const float* nk1w = (const float*)d_in[5]; const float* nk1b = (const float*)d_in[6];
    const float* nk2w = (const float*)d_in[7]; const float* nk2b = (const float*)d_in[8];
    const float* n2w = (const float*)d_in[9];  const float* n2b = (const float*)d_in[10];
    const float* q_w   = (const float*)d_in[11];
    const float* kv1_w = (const float*)d_in[12];
    const float* kv2_w = (const float*)d_in[13];
    const float* q_dw  = (const float*)d_in[14];
    const float* kv1_dw= (const float*)d_in[15];
    const float* kv2_dw= (const float*)d_in[16];
    const float* proj_w= (const float*)d_in[17];
    const float* temp1 = (const float*)d_in[18];
    const float* temp2 = (const float*)d_in[19];
    const float* pin_w = (const float*)d_in[20];
    const float* dw_w  = (const float*)d_in[21];
    const float* pout_w= (const float*)d_in[22];
    float* out = (float*)d_out;

    cudaFuncSetAttribute(gemm_mma<false>, cudaFuncAttributeMaxDynamicSharedMemorySize, GEMM_SMEM);
    cudaFuncSetAttribute(gemm_mma<true>,  cudaFuncAttributeMaxDynamicSharedMemorySize, GEMM_SMEM);
    cudaFuncSetAttribute(gemm3,            cudaFuncAttributeMaxDynamicSharedMemorySize, GEMM_SMEM);

    float *p_qpre, *p_q, *p_x2, *p_h;
    cudaGetSymbolAddress((void**)&p_qpre, g_qpre);
    cudaGetSymbolAddress((void**)&p_q, g_q);
    cudaGetSymbolAddress((void**)&p_x2, g_x2);
    cudaGetSymbolAddress((void**)&p_h, g_h);
    unsigned short *whi, *wlo, *ahi, *alo, *k1hi, *k1lo, *k2hi, *k2lo, *aohi, *aolo, *gghi, *gglo;
    cudaGetSymbolAddress((void**)&whi, g_whi);
    cudaGetSymbolAddress((void**)&wlo, g_wlo);
    cudaGetSymbolAddress((void**)&ahi, xt_a_hi);
    cudaGetSymbolAddress((void**)&alo, xt_a_lo);
    cudaGetSymbolAddress((void**)&k1hi, xt_k1_hi);
    cudaGetSymbolAddress((void**)&k1lo, xt_k1_lo);
    cudaGetSymbolAddress((void**)&k2hi, xt_k2_hi);
    cudaGetSymbolAddress((void**)&k2lo, xt_k2_lo);
    cudaGetSymbolAddress((void**)&aohi, xt_ao_hi);
    cudaGetSymbolAddress((void**)&aolo, xt_ao_lo);
    cudaGetSymbolAddress((void**)&gghi, xt_gg_hi);
    cudaGetSymbolAddress((void**)&gglo, xt_gg_lo);

    // 1: all weight conversions in one launch
    wconv_all<<<2556, 64>>>(q_w, kv1_w, kv2_w, proj_w, pin_w, pout_w);

    // 2-4: layernorms
    dim3 lnG(HWN / 1024, BB);
    ln_cp<<<lnG, 256>>>(x,     n1w,  n1b,  ahi,  alo);
    ln_cp<<<lnG, 256>>>(kv1in, nk1w, nk1b, k1hi, k1lo);
    ln_cp<<<lnG, 256>>>(kv2in, nk2w, nk2b, k2hi, k2lo);

    // 5: zero attention accumulators
    zero_attn<<<300, 256>>>();

    // 6: merged q/kv1/kv2 GEMM  (profiled launch)
    gemm3<<<dim3(HWN / 64, 3, 12), 256, GEMM_SMEM>>>();

    // 7-8: 3x3 grouped / depthwise
    dim3 dG(HWN / 1024, C2, BB);
    dwconv_g2<<<dG, 256>>>(p_qpre, q_dw, p_q);
    dim3 dKV(HWN / 1024, 2 * C2, BB);
    dwconv_kv<<<dKV, 256>>>(kv1_dw, kv2_dw);

    // 9-11: attention
    skernel<<<dim3(32, 16), 256>>>();
    softmax_kernel<<<32, 64>>>(temp1, temp2);
    av_cp<<<dim3(32, HWN / 256), 128>>>();

    // 12: proj (384 -> 192) + residual x
    dim3 gP(HWN / 64, 2, BB);
    gemm_mma<true><<<gP, 256, GEMM_SMEM>>>(whi + OFF_P, wlo + OFF_P, aohi, aolo, x, p_x2, 192, 384);

    // 13: FFN LN
    ln_cp<<<lnG, 256>>>(p_x2, n2w, n2b, ahi, alo);
    // 14: pin GEMM
    dim3 gIn(HWN / 64, 8, BB);
    gemm_mma<false><<<gIn, 256, GEMM_SMEM>>>(whi + OFF_PIN, wlo + OFF_PIN, ahi, alo, nullptr, p_h, 1020, 192);
    // 15: fused dwconv+gelu
    dim3 dGG(HWN / 1024, GGPAD, BB);
    dwgelu<<<dGG, 256>>>(p_h, dw_w, gghi, gglo);
    // 16: pout GEMM + residual
    gemm_mma<true><<<gP, 256, GEMM_SMEM>>>(whi + OFF_PO, wlo + OFF_PO, gghi, gglo, p_x2, out, 192, 512);
}

// round 8
// speedup vs baseline: 1.1724x; 1.1724x over previous
#include <cuda_runtime.h>
#include <cuda_bf16.h>
#include <math.h>

#define BB 4
#define CC 192
#define C2 384
#define HWN 16384
#define HIMG 128
#define CHD 48
#define HIDC 510
#define HID2 1020
#define GGPAD 512
#define EPSLN 1e-5f

__device__ __forceinline__ unsigned smem_u32(const void* p) {
    unsigned a;
    asm("{ .reg .u64 t; cvta.to.shared.u64 t, %1; cvt.u32.u64 %0, t; }"
        : "=r"(a) : "l"(p));
    return a;
}
#define CP_ASYNC16(dst, src) \
    asm volatile("cp.async.cg.shared.global [%0], [%1], 16;" :: "r"(dst), "l"(src))
#define CP_COMMIT() asm volatile("cp.async.commit_group;" ::: "memory")
#define CP_WAIT(n)  asm volatile("cp.async.wait_group %0;" :: "n"(n) : "memory")

__device__ __forceinline__ void ldm_x4(unsigned& r0, unsigned& r1, unsigned& r2, unsigned& r3,
                                       unsigned addr) {
    asm volatile("ldmatrix.sync.aligned.m8n8.x4.shared.b16 {%0,%1,%2,%3}, [%4];"
        : "=r"(r0), "=r"(r1), "=r"(r2), "=r"(r3) : "r"(addr));
}
__device__ __forceinline__ void ldm_x4_t(unsigned& r0, unsigned& r1, unsigned& r2, unsigned& r3,
                                         unsigned addr) {
    asm volatile("ldmatrix.sync.aligned.m8n8.x4.trans.shared.b16 {%0,%1,%2,%3}, [%4];"
        : "=r"(r0), "=r"(r1), "=r"(r2), "=r"(r3) : "r"(addr));
}
__device__ __forceinline__ void mma_bf(float* d, const unsigned* a, unsigned b0, unsigned b1) {
    asm volatile("mma.sync.aligned.m16n8k16.row.col.f32.bf16.bf16.f32 "
        "{%0,%1,%2,%3}, {%4,%5,%6,%7}, {%8,%9}, {%0,%1,%2,%3};"
        : "+f"(d[0]), "+f"(d[1]), "+f"(d[2]), "+f"(d[3])
        : "r"(a[0]), "r"(a[1]), "r"(a[2]), "r"(a[3]), "r"(b0), "r"(b1));
}

// ---------------- scratch ----------------
__device__ float g_qpre [BB*C2*HWN];
__device__ float g_kv1pre[BB*C2*HWN];
__device__ float g_kv2pre[BB*C2*HWN];
__device__ float g_q   [BB*C2*HWN];
__device__ float g_kv1 [BB*C2*HWN];
__device__ float g_kv2 [BB*C2*HWN];
__device__ float g_x2  [BB*CC*HWN];
__device__ float g_h   [BB*HID2*HWN];
__device__ float g_S   [32*CHD*CHD];
__device__ float g_nrm [32*2*CHD];

// bf16 hi/lo activations, natural layout: [b][channel][pixel]
__device__ __align__(16) unsigned short xt_a_hi [BB*CC*HWN];
__device__ __align__(16) unsigned short xt_a_lo [BB*CC*HWN];
__device__ __align__(16) unsigned short xt_k1_hi[BB*CC*HWN];
__device__ __align__(16) unsigned short xt_k1_lo[BB*CC*HWN];
__device__ __align__(16) unsigned short xt_k2_hi[BB*CC*HWN];
__device__ __align__(16) unsigned short xt_k2_lo[BB*CC*HWN];
__device__ __align__(16) unsigned short xt_ao_hi[BB*C2*HWN];
__device__ __align__(16) unsigned short xt_ao_lo[BB*C2*HWN];
__device__ __align__(16) unsigned short xt_gg_hi[BB*GGPAD*HWN];
__device__ __align__(16) unsigned short xt_gg_lo[BB*GGPAD*HWN];
// converted weights (row-major [O][Cpad])
#define OFF_Q   0
#define OFF_K1  (384*192)
#define OFF_K2  (2*384*192)
#define OFF_P   (3*384*192)
#define OFF_PIN (3*384*192 + 192*384)
#define OFF_PO  (3*384*192 + 192*384 + 1020*192)
#define WTOT    (3*384*192 + 192*384 + 1020*192 + 192*512)
#define WPAD    (64*512)
__device__ __align__(16) unsigned short g_whi[WTOT + WPAD];
__device__ __align__(16) unsigned short g_wlo[WTOT + WPAD];

// ---------------- fp32 -> bf16 hi/lo helpers ----------------
__device__ __forceinline__ void cvt2(float a, float b, unsigned& h, unsigned& l) {
    __nv_bfloat16 ha = __float2bfloat16_rn(a), hb = __float2bfloat16_rn(b);
    h = (unsigned)__bfloat16_as_ushort(ha) | ((unsigned)__bfloat16_as_ushort(hb) << 16);
    __nv_bfloat16 la = __float2bfloat16_rn(a - __bfloat162float(ha));
    __nv_bfloat16 lb = __float2bfloat16_rn(b - __bfloat162float(hb));
    l = (unsigned)__bfloat16_as_ushort(la) | ((unsigned)__bfloat16_as_ushort(lb) << 16);
}
__device__ __forceinline__ void cvt8(const float* v, uint4& hv, uint4& lv) {
    unsigned h[4], l[4];
    #pragma unroll
    for (int i = 0; i < 4; i++) cvt2(v[2*i], v[2*i+1], h[i], l[i]);
    hv = make_uint4(h[0], h[1], h[2], h[3]);
    lv = make_uint4(l[0], l[1], l[2], l[3]);
}

// ---------------- merged weight conversion (1 launch) ----------------
__global__ void wconv_all(const float* __restrict__ q_w, const float* __restrict__ kv1_w,
                          const float* __restrict__ kv2_w, const float* __restrict__ proj_w,
                          const float* __restrict__ pin_w, const float* __restrict__ pout_w) {
    int r = blockIdx.x;
    const float* W; int o, Cin, Cpad, off;
    if (r < 384)        { W = q_w;    o = r;        Cin = 192; Cpad = 192; off = OFF_Q; }
    else if (r < 768)   { W = kv1_w;  o = r - 384;  Cin = 192; Cpad = 192; off = OFF_K1; }
    else if (r < 1152)  { W = kv2_w;  o = r - 768;  Cin = 192; Cpad = 192; off = OFF_K2; }
    else if (r < 1344)  { W = proj_w; o = r - 1152; Cin = 384; Cpad = 384; off = OFF_P; }
    else if (r < 2364)  { W = pin_w;  o = r - 1344; Cin = 192; Cpad = 192; off = OFF_PIN; }
    else                { W = pout_w; o = r - 2364; Cin = 510; Cpad = 512; off = OFF_PO; }
    int c0 = threadIdx.x * 8;
    if (c0 >= Cpad) return;
    float v[8];
    #pragma unroll
    for (int j = 0; j < 8; j++) {
        int c = c0 + j;
        v[j] = (c < Cin) ? W[(size_t)o * Cin + c] : 0.f;
    }
    uint4 hv, lv; cvt8(v, hv, lv);
    *(uint4*)(g_whi + (size_t)off + (size_t)o * Cpad + c0) = hv;
    *(uint4*)(g_wlo + (size_t)off + (size_t)o * Cpad + c0) = lv;
}

// ======================= HMMA GEMM body =====================================
#define BK 32
#define ASTRIDE 40
#define PSTR 72
#define A_BYTES (128 * ASTRIDE * 2)
#define B_BYTES (BK * PSTR * 2)
#define BUF_BYTES (2 * A_BYTES + 2 * B_BYTES)
#define GEMM_SMEM (2 * BUF_BYTES)
#define YSTRIDE 68

template<bool RESID>
__device__ __forceinline__
void gemm_body(const unsigned short* __restrict__ Whi, const unsigned short* __restrict__ Wlo,
               const unsigned short* __restrict__ XhiB, const unsigned short* __restrict__ XloB,
               const float* __restrict__ R, float* __restrict__ Y, int O, int Cpad,
               int b, int p0, int o0, char* dsm) {
    unsigned sbase = smem_u32(dsm);
    int t = threadIdx.x, wid = t >> 5, lane = t & 31;
    int warpM = (wid >> 1) * 32;
    int warpN = (wid & 1) * 32;

    const unsigned short* WhiB = Whi + (size_t)o0 * Cpad;
    const unsigned short* WloB = Wlo + (size_t)o0 * Cpad;

    int nk = Cpad / BK;

    auto fill = [&](int kt) {
        int buf = kt & 1;
        unsigned bb = sbase + buf * BUF_BYTES;
        int k0 = kt * BK;
        #pragma unroll
        for (int j = 0; j < 6; j++) {
            int ci = j * 256 + t;
            if (ci < 1024) {
                int m = ci & 511;
                int row = m >> 2, g = m & 3;
                const unsigned short* src = ((ci < 512) ? WhiB : WloB)
                                            + (size_t)row * Cpad + k0 + g * 8;
                unsigned dst = bb + ((ci < 512) ? 0u : A_BYTES)
                             + (unsigned)(row * ASTRIDE + g * 8) * 2;
                CP_ASYNC16(dst, src);
            } else {
                int m = ci - 1024;
                int mm = m & 255;
                int row = mm >> 3, g = mm & 7;
                const unsigned short* src = ((m < 256) ? XhiB : XloB)
                                            + (size_t)(k0 + row) * HWN + g * 8;
                unsigned dst = bb + 2 * A_BYTES + ((m < 256) ? 0u : B_BYTES)
                             + (unsigned)(row * PSTR + g * 8) * 2;
                CP_ASYNC16(dst, src);
            }
        }
        CP_COMMIT();
    };

    float acc[2][4][4];
    #pragma unroll
    for (int i = 0; i < 2; i++)
        #pragma unroll
        for (int j = 0; j < 4; j++)
            #pragma unroll
            for (int k = 0; k < 4; k++) acc[i][j][k] = 0.f;

    fill(0);

    int rsel = lane & 15, csel = (lane >> 4) * 8;
    int bkr = (lane & 7) + ((lane >> 4) & 1) * 8;
    int bpc = ((lane >> 3) & 1) * 8;

    for (int kt = 0; kt < nk; kt++) {
        if (kt + 1 < nk) { fill(kt + 1); CP_WAIT(1); }
        else             { CP_WAIT(0); }
        __syncthreads();

        unsigned bb = sbase + (kt & 1) * BUF_BYTES;
        unsigned Ah = bb, Al = bb + A_BYTES;
        unsigned Bh = bb + 2 * A_BYTES, Bl = Bh + B_BYTES;

        #pragma unroll
        for (int kk = 0; kk < 2; kk++) {
            int kc = csel + kk * 16;
            unsigned ah[2][4], al[2][4], bh[2][4], bl[2][4];
            #pragma unroll
            for (int mt = 0; mt < 2; mt++) {
                unsigned off = (unsigned)((warpM + mt * 16 + rsel) * ASTRIDE + kc) * 2;
                ldm_x4(ah[mt][0], ah[mt][1], ah[mt][2], ah[mt][3], Ah + off);
                ldm_x4(al[mt][0], al[mt][1], al[mt][2], al[mt][3], Al + off);
            }
            #pragma unroll
            for (int np = 0; np < 2; np++) {
                unsigned off = (unsigned)((kk * 16 + bkr) * PSTR + warpN + np * 16 + bpc) * 2;
                ldm_x4_t(bh[np][0], bh[np][1], bh[np][2], bh[np][3], Bh + off);
                ldm_x4_t(bl[np][0], bl[np][1], bl[np][2], bl[np][3], Bl + off);
            }
            #pragma unroll
            for (int mt = 0; mt < 2; mt++)
                #pragma unroll
                for (int nt = 0; nt < 4; nt++) {
                    int np = nt >> 1, hf = nt & 1;
                    mma_bf(acc[mt][nt], ah[mt], bh[np][hf], bh[np][hf + 2]);
                    mma_bf(acc[mt][nt], ah[mt], bl[np][hf], bl[np][hf + 2]);
                    mma_bf(acc[mt][nt], al[mt], bh[np][hf], bh[np][hf + 2]);
                }
        }
        __syncthreads();
    }

    float* Ysm = (float*)dsm;
    #pragma unroll
    for (int mt = 0; mt < 2; mt++)
        #pragma unroll
        for (int nt = 0; nt < 4; nt++) {
            int r0 = warpM + mt * 16 + (lane >> 2);
            int cc = warpN + nt * 8 + (lane & 3) * 2;
            Ysm[r0 * YSTRIDE + cc]           = acc[mt][nt][0];
            Ysm[r0 * YSTRIDE + cc + 1]       = acc[mt][nt][1];
            Ysm[(r0 + 8) * YSTRIDE + cc]     = acc[mt][nt][2];
            Ysm[(r0 + 8) * YSTRIDE + cc + 1] = acc[mt][nt][3];
        }
    __syncthreads();
    #pragma unroll
    for (int i = 0; i < 8; i++) {
        int idx = i * 256 + t;
        int row = idx >> 4, c4 = (idx & 15) * 4;
        int o = o0 + row;
        if (o < O) {
            float4 v = *(float4*)(Ysm + row * YSTRIDE + c4);
            size_t goff = ((size_t)b * O + o) * HWN + p0 + c4;
            if (RESID) {
                float4 q = *(const float4*)(R + goff);
                v.x += q.x; v.y += q.y; v.z += q.z; v.w += q.w;
            }
            *(float4*)(Y + goff) = v;
        }
    }
}

template<bool RESID>
__global__ __launch_bounds__(256)
void gemm_mma(const unsigned short* __restrict__ Whi, const unsigned short* __restrict__ Wlo,
              const unsigned short* __restrict__ Xhi, const unsigned short* __restrict__ Xlo,
              const float* __restrict__ R, float* __restrict__ Y, int O, int Cpad) {
    extern __shared__ char dsm[];
    int b = blockIdx.z;
    gemm_body<RESID>(Whi, Wlo,
                     Xhi + (size_t)b * Cpad * HWN + blockIdx.x * 64,
                     Xlo + (size_t)b * Cpad * HWN + blockIdx.x * 64,
                     R, Y, O, Cpad, b, blockIdx.x * 64, blockIdx.y * 128, dsm);
}

// merged q/kv1/kv2 GEMM: grid (256, 3, 12); z: which = z>>2, b = z&3
__global__ __launch_bounds__(256)
void gemm3(void) {
    extern __shared__ char dsm[];
    int z = blockIdx.z, which = z >> 2, b = z & 3;
    const unsigned short *Whi, *Wlo, *Xhi, *Xlo;
    float* Y;
    if (which == 0)      { Whi = g_whi + OFF_Q;  Wlo = g_wlo + OFF_Q;  Xhi = xt_a_hi;  Xlo = xt_a_lo;  Y = g_qpre; }
    else if (which == 1) { Whi = g_whi + OFF_K1; Wlo = g_wlo + OFF_K1; Xhi = xt_k1_hi; Xlo = xt_k1_lo; Y = g_kv1pre; }
    else                 { Whi = g_whi + OFF_K2; Wlo = g_wlo + OFF_K2; Xhi = xt_k2_hi; Xlo = xt_k2_lo; Y = g_kv2pre; }
    gemm_body<false>(Whi, Wlo,
                     Xhi + (size_t)b * CC * HWN + blockIdx.x * 64,
                     Xlo + (size_t)b * CC * HWN + blockIdx.x * 64,
                     nullptr, Y, C2, CC, b, blockIdx.x * 64, blockIdx.y * 128, dsm);
}

// ---------------- LayerNorm -> bf16 hi/lo [c][p] ----------------------------
// block = 256 threads = 64 pixels x 4 channel-groups (48 ch each).
// One global read; register-resident normalize; 1024 blocks total.
__global__ __launch_bounds__(256)
void ln_cp(const float* __restrict__ X, const float* __restrict__ w,
           const float* __restrict__ bia,
           unsigned short* __restrict__ Hi, unsigned short* __restrict__ Lo) {
    __shared__ float2 red[256];
    int b = blockIdx.y;
    int px = threadIdx.x & 63, cg = threadIdx.x >> 6;
    int p = blockIdx.x * 64 + px;
    const float* xp = X + ((size_t)b * CC + (size_t)cg * 48) * HWN + p;
    float v[48];
    float s = 0.f, q = 0.f;
    #pragma unroll
    for (int i = 0; i < 48; i++) {
        float t = xp[(size_t)i * HWN];
        v[i] = t; s += t; q += t * t;
    }
    red[threadIdx.x] = make_float2(s, q);
    __syncthreads();
    float2 r0 = red[px], r1 = red[64 + px], r2 = red[128 + px], r3 = red[192 + px];
    float st = r0.x + r1.x + r2.x + r3.x;
    float qt = r0.y + r1.y + r2.y + r3.y;
    const float invc = 1.f / CC;
    float mu = st * invc;
    float iv = rsqrtf(fmaxf(qt * invc - mu * mu, 0.f) + EPSLN);
    size_t base = ((size_t)b * CC + (size_t)cg * 48) * HWN + p;
    #pragma unroll
    for (int i = 0; i < 48; i++) {
        int c = cg * 48 + i;
        float o = (v[i] - mu) * iv * w[c] + bia[c];
        __nv_bfloat16 hb = __float2bfloat16_rn(o);
        Hi[base + (size_t)i * HWN] = __bfloat16_as_ushort(hb);
        __nv_bfloat16 lb = __float2bfloat16_rn(o - __bfloat162float(hb));
        Lo[base + (size_t)i * HWN] = __bfloat16_as_ushort(lb);
    }
}

// ---------------- depthwise 3x3 core ----------------
__device__ __forceinline__ void dw_core(const float* __restrict__ xp, const float* kv,
                                        int h, int wcol, float& a0, float& a1,
                                        float& a2, float& a3) {
    #pragma unroll
    for (int dy = -1; dy <= 1; dy++) {
        int hh = h + dy;
        if (hh < 0 || hh >= HIMG) continue;
        const float* r = xp + hh * HIMG + wcol;
        float4 m = *(const float4*)r;
        float lf = (wcol > 0) ? r[-1] : 0.f;
        float rt = (wcol < 124) ? r[4] : 0.f;
        const float* k = kv + (dy + 1) * 3;
        a0 += k[0]*lf  + k[1]*m.x + k[2]*m.y;
        a1 += k[0]*m.x + k[1]*m.y + k[2]*m.z;
        a2 += k[0]*m.y + k[1]*m.z + k[2]*m.w;
        a3 += k[0]*m.z + k[1]*m.w + k[2]*rt;
    }
}

// merged kv1+kv2 depthwise (grid.y = 768)
__global__ void dwconv_kv(const float* __restrict__ Wt1, const float* __restrict__ Wt2) {
    int b = blockIdx.z, cc = blockIdx.y;
    int p = (blockIdx.x * 256 + threadIdx.x) * 4;
    int h = p >> 7, wcol = p & 127;
    const float* X; const float* Wt; float* Y; int c;
    if (cc < C2) { X = g_kv1pre; Wt = Wt1; Y = g_kv1; c = cc; }
    else         { X = g_kv2pre; Wt = Wt2; Y = g_kv2; c = cc - C2; }
    const float* xp = X + ((size_t)b * C2 + c) * HWN;
    float kv[9];
    #pragma unroll
    for (int i = 0; i < 9; i++) kv[i] = Wt[(size_t)c * 9 + i];
    float a0 = 0, a1 = 0, a2 = 0, a3 = 0;
    dw_core(xp, kv, h, wcol, a0, a1, a2, a3);
    *(float4*)(Y + ((size_t)b * C2 + c) * HWN + p) = make_float4(a0, a1, a2, a3);
}

__global__ void dwconv_g2(const float* __restrict__ X, const float* __restrict__ Wt,
                          float* __restrict__ Y) {
    int b = blockIdx.z, o = blockIdx.y;
    int p = (blockIdx.x * 256 + threadIdx.x) * 4;
    int h = p >> 7, wcol = p & 127;
    int i0 = (o >> 1) << 1;
    const float* x0 = X + ((size_t)b * C2 + i0) * HWN;
    float kv[18];
    #pragma unroll
    for (int i = 0; i < 18; i++) kv[i] = Wt[(size_t)o * 18 + i];
    float a0 = 0, a1 = 0, a2 = 0, a3 = 0;
    dw_core(x0, kv, h, wcol, a0, a1, a2, a3);
    dw_core(x0 + HWN, kv + 9, h, wcol, a0, a1, a2, a3);
    *(float4*)(Y + ((size_t)b * C2 + o) * HWN + p) = make_float4(a0, a1, a2, a3);
}

// ---------------- fused FFN dwconv + gated gelu -> bf16 [c][p] --------------
__global__ void dwgelu(const float* __restrict__ X, const float* __restrict__ Wt,
                       unsigned short* __restrict__ Hi, unsigned short* __restrict__ Lo) {
    int b = blockIdx.z, c = blockIdx.y;
    int p = (blockIdx.x * 256 + threadIdx.x) * 4;
    size_t oidx = ((size_t)b * GGPAD + c) * HWN + p;
    if (c >= HIDC) {
        *(uint2*)(Hi + oidx) = make_uint2(0, 0);
        *(uint2*)(Lo + oidx) = make_uint2(0, 0);
        return;
    }
    int h = p >> 7, wcol = p & 127;
    float va[8];
    #pragma unroll
    for (int half = 0; half < 2; half++) {
        int ch = c + half * HIDC;
        const float* xp = X + ((size_t)b * HID2 + ch) * HWN;
        float kv[9];
        #pragma unroll
        for (int i = 0; i < 9; i++) kv[i] = Wt[(size_t)ch * 9 + i];
        float a0 = 0, a1 = 0, a2 = 0, a3 = 0;
        dw_core(xp, kv, h, wcol, a0, a1, a2, a3);
        va[half*4+0] = a0; va[half*4+1] = a1; va[half*4+2] = a2; va[half*4+3] = a3;
    }
    float o[4];
    #pragma unroll
    for (int j = 0; j < 4; j++) {
        float a = va[j];
        float ge = 0.5f * a * (1.f + erff(a * 0.70710678118654752f));
        o[j] = ge * va[4+j];
    }
    unsigned h0, l0, h1, l1;
    cvt2(o[0], o[1], h0, l0);
    cvt2(o[2], o[3], h1, l1);
    *(uint2*)(Hi + oidx) = make_uint2(h0, h1);
    *(uint2*)(Lo + oidx) = make_uint2(l0, l1);
}

// ---------------- attention ----------------
__global__ void zero_attn() {
    int i = blockIdx.x * 256 + threadIdx.x;
    if (i < 32 * CHD * CHD) g_S[i] = 0.f;
    if (i < 32 * 96) g_nrm[i] = 0.f;
}

__global__ void skernel() {
    int m = blockIdx.x, ns = blockIdx.y;
    int b = m >> 3, br = (m >> 2) & 1, hh = m & 3;
    const float* qb = g_q + ((size_t)b * C2 + br * CC + hh * CHD) * HWN;
    const float* kb = (br ? g_kv2 : g_kv1) + ((size_t)b * C2 + hh * CHD) * HWN;
    __shared__ float Qs[CHD][65];
    __shared__ float Ks[CHD][65];
    int t = threadIdx.x;
    int tx = t & 15, ty = t >> 4;
    float acc[3][3];
    #pragma unroll
    for (int i = 0; i < 3; i++)
        #pragma unroll
        for (int j = 0; j < 3; j++) acc[i][j] = 0.f;
    const float* nrow = (t < CHD) ? &Qs[t][0] : ((t < 96) ? &Ks[t - CHD][0] : (const float*)0);
    float nacc = 0.f;
    int nbeg = ns * 1024;
    for (int n0 = nbeg; n0 < nbeg + 1024; n0 += 64) {
        #pragma unroll
        for (int i = t; i < CHD * 64; i += 256) {
            int rr = i >> 6, cc = i & 63;
            Qs[rr][cc] = qb[(size_t)rr * HWN + n0 + cc];
            Ks[rr][cc] = kb[(size_t)rr * HWN + n0 + cc];
        }
        __syncthreads();
        if (nrow) {
            #pragma unroll 8
            for (int cc = 0; cc < 64; cc++) { float v = nrow[cc]; nacc += v * v; }
        }
        #pragma unroll 8
        for (int kk = 0; kk < 64; kk++) {
            float qv[3], kvv[3];
            #pragma unroll
            for (int i = 0; i < 3; i++) qv[i] = Qs[ty + 16 * i][kk];
            #pragma unroll
            for (int j = 0; j < 3; j++) kvv[j] = Ks[tx + 16 * j][kk];
            #pragma unroll
            for (int i = 0; i < 3; i++)
                #pragma unroll
                for (int j = 0; j < 3; j++) acc[i][j] += qv[i] * kvv[j];
        }
        __syncthreads();
    }
    #pragma unroll
    for (int i = 0; i < 3; i++)
        #pragma unroll
        for (int j = 0; j < 3; j++)
            atomicAdd(&g_S[m * CHD * CHD + (ty + 16 * i) * CHD + (tx + 16 * j)], acc[i][j]);
    if (t < 96) atomicAdd(&g_nrm[m * 96 + t], nacc);
}

__global__ void softmax_kernel(const float* __restrict__ t1, const float* __restrict__ t2) {
    int m = blockIdx.x;
    int c = threadIdx.x;
    __shared__ float nk[CHD];
    if (c < CHD) nk[c] = fmaxf(sqrtf(g_nrm[m * 96 + CHD + c]), 1e-12f);
    __syncthreads();
    if (c >= CHD) return;
    int br = (m >> 2) & 1, hh = m & 3;
    float tmp = (br ? t2 : t1)[hh];
    float nq = fmaxf(sqrtf(g_nrm[m * 96 + c]), 1e-12f);
    float* row = g_S + (size_t)m * CHD * CHD + c * CHD;
    float vals[CHD];
    float mx = -1e30f;
    #pragma unroll
    for (int d = 0; d < CHD; d++) {
        float v = row[d] / (nq * nk[d]) * tmp;
        vals[d] = v;
        mx = fmaxf(mx, v);
    }
    float sum = 0.f;
    #pragma unroll
    for (int d = 0; d < CHD; d++) { vals[d] = __expf(vals[d] - mx); sum += vals[d]; }
    float inv = 1.f / sum;
    #pragma unroll
    for (int d = 0; d < CHD; d++) row[d] = vals[d] * inv;
}

__global__ void av_cp() {
    int m = blockIdx.x;
    int b = m >> 3, br = (m >> 2) & 1, hh = m & 3;
    __shared__ float As[CHD * CHD];
    for (int i = threadIdx.x; i < CHD * CHD; i += 128) As[i] = g_S[(size_t)m * CHD * CHD + i];
    __syncthreads();
    const float* vb = (br ? g_kv2 : g_kv1) + ((size_t)b * C2 + CC + hh * CHD) * HWN;
    int p = blockIdx.y * 256 + threadIdx.x * 2;
    float acc0[CHD], acc1[CHD];
    #pragma unroll
    for (int c = 0; c < CHD; c++) { acc0[c] = 0.f; acc1[c] = 0.f; }
    for (int d = 0; d < CHD; d++) {
        float2 v = *(const float2*)(vb + (size_t)d * HWN + p);
        #pragma unroll
        for (int c = 0; c < CHD; c++) {
            float a = As[c * CHD + d];
            acc0[c] += a * v.x;
            acc1[c] += a * v.y;
        }
    }
    int off = br * CC + hh * CHD;
    size_t base = ((size_t)b * C2 + off) * HWN + p;
    #pragma unroll
    for (int c = 0; c < CHD; c++) {
        unsigned h, l; cvt2(acc0[c], acc1[c], h, l);
        *(unsigned*)(xt_ao_hi + base + (size_t)c * HWN) = h;
        *(unsigned*)(xt_ao_lo + base + (size_t)c * HWN) = l;
    }
}

// ---------------- launch ----------------
extern "C" void kernel_launch(void* const* d_in, const int* in_sizes, int n_in,
                              void* d_out, int out_size) {
    const float* x       = (const float*)d_in[0];
    const float* kv1in   = (const float*)d_in[1];
    const float* kv2in   = (const float*)d_in[2];
    const float* n1w = (const float*)d_in[3];  const float* n1b = (const float*)d_in[4];
    const float* nk1w = (const float*)d_in[5]; const float* nk1b = (const float*)d_in[6];
    const float* nk2w = (const float*)d_in[7]; const float* nk2b = (const float*)d_in[8];
    const float* n2w = (const float*)d_in[9];  const float* n2b = (const float*)d_in[10];
    const float* q_w   = (const float*)d_in[11];
    const float* kv1_w = (const float*)d_in[12];
    const float* kv2_w = (const float*)d_in[13];
    const float* q_dw  = (const float*)d_in[14];
    const float* kv1_dw= (const float*)d_in[15];
    const float* kv2_dw= (const float*)d_in[16];
    const float* proj_w= (const float*)d_in[17];
    const float* temp1 = (const float*)d_in[18];
    const float* temp2 = (const float*)d_in[19];
    const float* pin_w = (const float*)d_in[20];
    const float* dw_w  = (const float*)d_in[21];
    const float* pout_w= (const float*)d_in[22];
    float* out = (float*)d_out;

    cudaFuncSetAttribute(gemm_mma<false>, cudaFuncAttributeMaxDynamicSharedMemorySize, GEMM_SMEM);
    cudaFuncSetAttribute(gemm_mma<true>,  cudaFuncAttributeMaxDynamicSharedMemorySize, GEMM_SMEM);
    cudaFuncSetAttribute(gemm3,            cudaFuncAttributeMaxDynamicSharedMemorySize, GEMM_SMEM);

    float *p_qpre, *p_q, *p_x2, *p_h;
    cudaGetSymbolAddress((void**)&p_qpre, g_qpre);
    cudaGetSymbolAddress((void**)&p_q, g_q);
    cudaGetSymbolAddress((void**)&p_x2, g_x2);
    cudaGetSymbolAddress((void**)&p_h, g_h);
    unsigned short *whi, *wlo, *ahi, *alo, *k1hi, *k1lo, *k2hi, *k2lo, *aohi, *aolo, *gghi, *gglo;
    cudaGetSymbolAddress((void**)&whi, g_whi);
    cudaGetSymbolAddress((void**)&wlo, g_wlo);
    cudaGetSymbolAddress((void**)&ahi, xt_a_hi);
    cudaGetSymbolAddress((void**)&alo, xt_a_lo);
    cudaGetSymbolAddress((void**)&k1hi, xt_k1_hi);
    cudaGetSymbolAddress((void**)&k1lo, xt_k1_lo);
    cudaGetSymbolAddress((void**)&k2hi, xt_k2_hi);
    cudaGetSymbolAddress((void**)&k2lo, xt_k2_lo);
    cudaGetSymbolAddress((void**)&aohi, xt_ao_hi);
    cudaGetSymbolAddress((void**)&aolo, xt_ao_lo);
    cudaGetSymbolAddress((void**)&gghi, xt_gg_hi);
    cudaGetSymbolAddress((void**)&gglo, xt_gg_lo);

    // 1: all weight conversions in one launch
    wconv_all<<<2556, 64>>>(q_w, kv1_w, kv2_w, proj_w, pin_w, pout_w);

    // 2-4: layernorms (64 px x 4 cgroups per block; 1024 blocks each)
    dim3 lnG(HWN / 64, BB);
    ln_cp<<<lnG, 256>>>(x,     n1w,  n1b,  ahi,  alo);
    ln_cp<<<lnG, 256>>>(kv1in, nk1w, nk1b, k1hi, k1lo);
    ln_cp<<<lnG, 256>>>(kv2in, nk2w, nk2b, k2hi, k2lo);

    // 5: zero attention accumulators
    zero_attn<<<300, 256>>>();

    // 6: merged q/kv1/kv2 GEMM
    gemm3<<<dim3(HWN / 64, 3, 12), 256, GEMM_SMEM>>>();

    // 7-8: 3x3 grouped / depthwise
    dim3 dG(HWN / 1024, C2, BB);
    dwconv_g2<<<dG, 256>>>(p_qpre, q_dw, p_q);
    dim3 dKV(HWN / 1024, 2 * C2, BB);
    dwconv_kv<<<dKV, 256>>>(kv1_dw, kv2_dw);

    // 9-11: attention
    skernel<<<dim3(32, 16), 256>>>();
    softmax_kernel<<<32, 64>>>(temp1, temp2);
    av_cp<<<dim3(32, HWN / 256), 128>>>();

    // 12: proj (384 -> 192) + residual x
    dim3 gP(HWN / 64, 2, BB);
    gemm_mma<true><<<gP, 256, GEMM_SMEM>>>(whi + OFF_P, wlo + OFF_P, aohi, aolo, x, p_x2, 192, 384);

    // 13: FFN LN
    ln_cp<<<lnG, 256>>>(p_x2, n2w, n2b, ahi, alo);
    // 14: pin GEMM
    dim3 gIn(HWN / 64, 8, BB);
    gemm_mma<false><<<gIn, 256, GEMM_SMEM>>>(whi + OFF_PIN, wlo + OFF_PIN, ahi, alo, nullptr, p_h, 1020, 192);
    // 15: fused dwconv+gelu
    dim3 dGG(HWN / 1024, GGPAD, BB);
    dwgelu<<<dGG, 256>>>(p_h, dw_w, gghi, gglo);
    // 16: pout GEMM + residual
    gemm_mma<true><<<gP, 256, GEMM_SMEM>>>(whi + OFF_PO, wlo + OFF_PO, gghi, gglo, p_x2, out, 192, 512);
}

// round 9
// speedup vs baseline: 1.1786x; 1.0053x over previous
#include <cuda_runtime.h>
#include <cuda_bf16.h>
#include <cuda_fp16.h>
#include <math.h>

#define BB 4
#define CC 192
#define C2 384
#define HWN 16384
#define HIMG 128
#define CHD 48
#define HIDC 510
#define HID2 1020
#define GGPAD 512
#define EPSLN 1e-5f

__device__ __forceinline__ unsigned smem_u32(const void* p) {
    unsigned a;
    asm("{ .reg .u64 t; cvta.to.shared.u64 t, %1; cvt.u32.u64 %0, t; }"
        : "=r"(a) : "l"(p));
    return a;
}
#define CP_ASYNC16(dst, src) \
    asm volatile("cp.async.cg.shared.global [%0], [%1], 16;" :: "r"(dst), "l"(src))
#define CP_COMMIT() asm volatile("cp.async.commit_group;" ::: "memory")
#define CP_WAIT(n)  asm volatile("cp.async.wait_group %0;" :: "n"(n) : "memory")

__device__ __forceinline__ void ldm_x4(unsigned& r0, unsigned& r1, unsigned& r2, unsigned& r3,
                                       unsigned addr) {
    asm volatile("ldmatrix.sync.aligned.m8n8.x4.shared.b16 {%0,%1,%2,%3}, [%4];"
        : "=r"(r0), "=r"(r1), "=r"(r2), "=r"(r3) : "r"(addr));
}
__device__ __forceinline__ void ldm_x4_t(unsigned& r0, unsigned& r1, unsigned& r2, unsigned& r3,
                                         unsigned addr) {
    asm volatile("ldmatrix.sync.aligned.m8n8.x4.trans.shared.b16 {%0,%1,%2,%3}, [%4];"
        : "=r"(r0), "=r"(r1), "=r"(r2), "=r"(r3) : "r"(addr));
}
__device__ __forceinline__ void mma_bf(float* d, const unsigned* a, unsigned b0, unsigned b1) {
    asm volatile("mma.sync.aligned.m16n8k16.row.col.f32.bf16.bf16.f32 "
        "{%0,%1,%2,%3}, {%4,%5,%6,%7}, {%8,%9}, {%0,%1,%2,%3};"
        : "+f"(d[0]), "+f"(d[1]), "+f"(d[2]), "+f"(d[3])
        : "r"(a[0]), "r"(a[1]), "r"(a[2]), "r"(a[3]), "r"(b0), "r"(b1));
}

// ---------------- scratch (fp16 intermediates, fp32 residual chain) ---------
__device__ __align__(16) __half g_qpre [BB*C2*HWN];
__device__ __align__(16) __half g_kv1pre[BB*C2*HWN];
__device__ __align__(16) __half g_kv2pre[BB*C2*HWN];
__device__ __align__(16) __half g_q   [BB*C2*HWN];
__device__ __align__(16) __half g_kv1 [BB*C2*HWN];
__device__ __align__(16) __half g_kv2 [BB*C2*HWN];
__device__ __align__(16) __half g_h   [BB*HID2*HWN];
__device__ float g_x2  [BB*CC*HWN];
__device__ float g_S   [32*CHD*CHD];
__device__ float g_nrm [32*2*CHD];

// bf16 hi/lo activations, natural layout: [b][channel][pixel]
__device__ __align__(16) unsigned short xt_a_hi [BB*CC*HWN];
__device__ __align__(16) unsigned short xt_a_lo [BB*CC*HWN];
__device__ __align__(16) unsigned short xt_k1_hi[BB*CC*HWN];
__device__ __align__(16) unsigned short xt_k1_lo[BB*CC*HWN];
__device__ __align__(16) unsigned short xt_k2_hi[BB*CC*HWN];
__device__ __align__(16) unsigned short xt_k2_lo[BB*CC*HWN];
__device__ __align__(16) unsigned short xt_ao_hi[BB*C2*HWN];
__device__ __align__(16) unsigned short xt_ao_lo[BB*C2*HWN];
__device__ __align__(16) unsigned short xt_gg_hi[BB*GGPAD*HWN];
__device__ __align__(16) unsigned short xt_gg_lo[BB*GGPAD*HWN];
// converted weights (row-major [O][Cpad])
#define OFF_Q   0
#define OFF_K1  (384*192)
#define OFF_K2  (2*384*192)
#define OFF_P   (3*384*192)
#define OFF_PIN (3*384*192 + 192*384)
#define OFF_PO  (3*384*192 + 192*384 + 1020*192)
#define WTOT    (3*384*192 + 192*384 + 1020*192 + 192*512)
#define WPAD    (64*512)
__device__ __align__(16) unsigned short g_whi[WTOT + WPAD];
__device__ __align__(16) unsigned short g_wlo[WTOT + WPAD];

// ---------------- fp32 -> bf16 hi/lo helpers ----------------
__device__ __forceinline__ void cvt2(float a, float b, unsigned& h, unsigned& l) {
    __nv_bfloat16 ha = __float2bfloat16_rn(a), hb = __float2bfloat16_rn(b);
    h = (unsigned)__bfloat16_as_ushort(ha) | ((unsigned)__bfloat16_as_ushort(hb) << 16);
    __nv_bfloat16 la = __float2bfloat16_rn(a - __bfloat162float(ha));
    __nv_bfloat16 lb = __float2bfloat16_rn(b - __bfloat162float(hb));
    l = (unsigned)__bfloat16_as_ushort(la) | ((unsigned)__bfloat16_as_ushort(lb) << 16);
}
__device__ __forceinline__ void cvt8(const float* v, uint4& hv, uint4& lv) {
    unsigned h[4], l[4];
    #pragma unroll
    for (int i = 0; i < 4; i++) cvt2(v[2*i], v[2*i+1], h[i], l[i]);
    hv = make_uint4(h[0], h[1], h[2], h[3]);
    lv = make_uint4(l[0], l[1], l[2], l[3]);
}

// ---------------- merged weight conversion (1 launch) ----------------
__global__ void wconv_all(const float* __restrict__ q_w, const float* __restrict__ kv1_w,
                          const float* __restrict__ kv2_w, const float* __restrict__ proj_w,
                          const float* __restrict__ pin_w, const float* __restrict__ pout_w) {
    int r = blockIdx.x;
    const float* W; int o, Cin, Cpad, off;
    if (r < 384)        { W = q_w;    o = r;        Cin = 192; Cpad = 192; off = OFF_Q; }
    else if (r < 768)   { W = kv1_w;  o = r - 384;  Cin = 192; Cpad = 192; off = OFF_K1; }
    else if (r < 1152)  { W = kv2_w;  o = r - 768;  Cin = 192; Cpad = 192; off = OFF_K2; }
    else if (r < 1344)  { W = proj_w; o = r - 1152; Cin = 384; Cpad = 384; off = OFF_P; }
    else if (r < 2364)  { W = pin_w;  o = r - 1344; Cin = 192; Cpad = 192; off = OFF_PIN; }
    else                { W = pout_w; o = r - 2364; Cin = 510; Cpad = 512; off = OFF_PO; }
    int c0 = threadIdx.x * 8;
    if (c0 >= Cpad) return;
    float v[8];
    #pragma unroll
    for (int j = 0; j < 8; j++) {
        int c = c0 + j;
        v[j] = (c < Cin) ? W[(size_t)o * Cin + c] : 0.f;
    }
    uint4 hv, lv; cvt8(v, hv, lv);
    *(uint4*)(g_whi + (size_t)off + (size_t)o * Cpad + c0) = hv;
    *(uint4*)(g_wlo + (size_t)off + (size_t)o * Cpad + c0) = lv;
}

// ======================= HMMA GEMM body =====================================
#define BK 32
#define ASTRIDE 40
#define PSTR 72
#define A_BYTES (128 * ASTRIDE * 2)
#define B_BYTES (BK * PSTR * 2)
#define BUF_BYTES (2 * A_BYTES + 2 * B_BYTES)
#define GEMM_SMEM (2 * BUF_BYTES)
#define YSTRIDE 68

template<bool RESID, bool HALF_OUT>
__device__ __forceinline__
void gemm_body(const unsigned short* __restrict__ Whi, const unsigned short* __restrict__ Wlo,
               const unsigned short* __restrict__ XhiB, const unsigned short* __restrict__ XloB,
               const float* __restrict__ R, void* __restrict__ Yv, int O, int Cpad,
               int b, int p0, int o0, char* dsm) {
    unsigned sbase = smem_u32(dsm);
    int t = threadIdx.x, wid = t >> 5, lane = t & 31;
    int warpM = (wid >> 1) * 32;
    int warpN = (wid & 1) * 32;

    const unsigned short* WhiB = Whi + (size_t)o0 * Cpad;
    const unsigned short* WloB = Wlo + (size_t)o0 * Cpad;

    int nk = Cpad / BK;

    auto fill = [&](int kt) {
        int buf = kt & 1;
        unsigned bb = sbase + buf * BUF_BYTES;
        int k0 = kt * BK;
        #pragma unroll
        for (int j = 0; j < 6; j++) {
            int ci = j * 256 + t;
            if (ci < 1024) {
                int m = ci & 511;
                int row = m >> 2, g = m & 3;
                const unsigned short* src = ((ci < 512) ? WhiB : WloB)
                                            + (size_t)row * Cpad + k0 + g * 8;
                unsigned dst = bb + ((ci < 512) ? 0u : A_BYTES)
                             + (unsigned)(row * ASTRIDE + g * 8) * 2;
                CP_ASYNC16(dst, src);
            } else {
                int m = ci - 1024;
                int mm = m & 255;
                int row = mm >> 3, g = mm & 7;
                const unsigned short* src = ((m < 256) ? XhiB : XloB)
                                            + (size_t)(k0 + row) * HWN + g * 8;
                unsigned dst = bb + 2 * A_BYTES + ((m < 256) ? 0u : B_BYTES)
                             + (unsigned)(row * PSTR + g * 8) * 2;
                CP_ASYNC16(dst, src);
            }
        }
        CP_COMMIT();
    };

    float acc[2][4][4];
    #pragma unroll
    for (int i = 0; i < 2; i++)
        #pragma unroll
        for (int j = 0; j < 4; j++)
            #pragma unroll
            for (int k = 0; k < 4; k++) acc[i][j][k] = 0.f;

    fill(0);

    int rsel = lane & 15, csel = (lane >> 4) * 8;
    int bkr = (lane & 7) + ((lane >> 4) & 1) * 8;
    int bpc = ((lane >> 3) & 1) * 8;

    for (int kt = 0; kt < nk; kt++) {
        if (kt + 1 < nk) { fill(kt + 1); CP_WAIT(1); }
        else             { CP_WAIT(0); }
        __syncthreads();

        unsigned bb = sbase + (kt & 1) * BUF_BYTES;
        unsigned Ah = bb, Al = bb + A_BYTES;
        unsigned Bh = bb + 2 * A_BYTES, Bl = Bh + B_BYTES;

        #pragma unroll
        for (int kk = 0; kk < 2; kk++) {
            int kc = csel + kk * 16;
            unsigned ah[2][4], al[2][4], bh[2][4], bl[2][4];
            #pragma unroll
            for (int mt = 0; mt < 2; mt++) {
                unsigned off = (unsigned)((warpM + mt * 16 + rsel) * ASTRIDE + kc) * 2;
                ldm_x4(ah[mt][0], ah[mt][1], ah[mt][2], ah[mt][3], Ah + off);
                ldm_x4(al[mt][0], al[mt][1], al[mt][2], al[mt][3], Al + off);
            }
            #pragma unroll
            for (int np = 0; np < 2; np++) {
                unsigned off = (unsigned)((kk * 16 + bkr) * PSTR + warpN + np * 16 + bpc) * 2;
                ldm_x4_t(bh[np][0], bh[np][1], bh[np][2], bh[np][3], Bh + off);
                ldm_x4_t(bl[np][0], bl[np][1], bl[np][2], bl[np][3], Bl + off);
            }
            #pragma unroll
            for (int mt = 0; mt < 2; mt++)
                #pragma unroll
                for (int nt = 0; nt < 4; nt++) {
                    int np = nt >> 1, hf = nt & 1;
                    mma_bf(acc[mt][nt], ah[mt], bh[np][hf], bh[np][hf + 2]);
                    mma_bf(acc[mt][nt], ah[mt], bl[np][hf], bl[np][hf + 2]);
                    mma_bf(acc[mt][nt], al[mt], bh[np][hf], bh[np][hf + 2]);
                }
        }
        __syncthreads();
    }

    float* Ysm = (float*)dsm;
    #pragma unroll
    for (int mt = 0; mt < 2; mt++)
        #pragma unroll
        for (int nt = 0; nt < 4; nt++) {
            int r0 = warpM + mt * 16 + (lane >> 2);
            int cc = warpN + nt * 8 + (lane & 3) * 2;
            Ysm[r0 * YSTRIDE + cc]           = acc[mt][nt][0];
            Ysm[r0 * YSTRIDE + cc + 1]       = acc[mt][nt][1];
            Ysm[(r0 + 8) * YSTRIDE + cc]     = acc[mt][nt][2];
            Ysm[(r0 + 8) * YSTRIDE + cc + 1] = acc[mt][nt][3];
        }
    __syncthreads();
    #pragma unroll
    for (int i = 0; i < 8; i++) {
        int idx = i * 256 + t;
        int row = idx >> 4, c4 = (idx & 15) * 4;
        int o = o0 + row;
        if (o < O) {
            float4 v = *(float4*)(Ysm + row * YSTRIDE + c4);
            size_t goff = ((size_t)b * O + o) * HWN + p0 + c4;
            if (HALF_OUT) {
                __half2 h01 = __floats2half2_rn(v.x, v.y);
                __half2 h23 = __floats2half2_rn(v.z, v.w);
                uint2 u;
                u.x = *(unsigned*)&h01;
                u.y = *(unsigned*)&h23;
                *(uint2*)((__half*)Yv + goff) = u;
            } else {
                if (RESID) {
                    float4 q = *(const float4*)(R + goff);
                    v.x += q.x; v.y += q.y; v.z += q.z; v.w += q.w;
                }
                *(float4*)((float*)Yv + goff) = v;
            }
        }
    }
}

template<bool RESID, bool HALF_OUT>
__global__ __launch_bounds__(256)
void gemm_mma(const unsigned short* __restrict__ Whi, const unsigned short* __restrict__ Wlo,
              const unsigned short* __restrict__ Xhi, const unsigned short* __restrict__ Xlo,
              const float* __restrict__ R, void* __restrict__ Y, int O, int Cpad) {
    extern __shared__ char dsm[];
    int b = blockIdx.z;
    gemm_body<RESID, HALF_OUT>(Whi, Wlo,
                     Xhi + (size_t)b * Cpad * HWN + blockIdx.x * 64,
                     Xlo + (size_t)b * Cpad * HWN + blockIdx.x * 64,
                     R, Y, O, Cpad, b, blockIdx.x * 64, blockIdx.y * 128, dsm);
}

// merged q/kv1/kv2 GEMM: grid (256, 3, 12); z: which = z>>2, b = z&3
__global__ __launch_bounds__(256)
void gemm3(void) {
    extern __shared__ char dsm[];
    int z = blockIdx.z, which = z >> 2, b = z & 3;
    const unsigned short *Whi, *Wlo, *Xhi, *Xlo;
    __half* Y;
    if (which == 0)      { Whi = g_whi + OFF_Q;  Wlo = g_wlo + OFF_Q;  Xhi = xt_a_hi;  Xlo = xt_a_lo;  Y = g_qpre; }
    else if (which == 1) { Whi = g_whi + OFF_K1; Wlo = g_wlo + OFF_K1; Xhi = xt_k1_hi; Xlo = xt_k1_lo; Y = g_kv1pre; }
    else                 { Whi = g_whi + OFF_K2; Wlo = g_wlo + OFF_K2; Xhi = xt_k2_hi; Xlo = xt_k2_lo; Y = g_kv2pre; }
    gemm_body<false, true>(Whi, Wlo,
                     Xhi + (size_t)b * CC * HWN + blockIdx.x * 64,
                     Xlo + (size_t)b * CC * HWN + blockIdx.x * 64,
                     nullptr, Y, C2, CC, b, blockIdx.x * 64, blockIdx.y * 128, dsm);
}

// ---------------- LayerNorm -> bf16 hi/lo [c][p] ----------------------------
// block = 256 threads = 64 pixels x 4 channel-groups (48 ch each).
__device__ __forceinline__
void ln_body(const float* __restrict__ X, const float* __restrict__ w,
             const float* __restrict__ bia,
             unsigned short* __restrict__ Hi, unsigned short* __restrict__ Lo,
             int b, int pblk) {
    __shared__ float2 red[256];
    int px = threadIdx.x & 63, cg = threadIdx.x >> 6;
    int p = pblk * 64 + px;
    const float* xp = X + ((size_t)b * CC + (size_t)cg * 48) * HWN + p;
    float v[48];
    float s = 0.f, q = 0.f;
    #pragma unroll
    for (int i = 0; i < 48; i++) {
        float t = xp[(size_t)i * HWN];
        v[i] = t; s += t; q += t * t;
    }
    red[threadIdx.x] = make_float2(s, q);
    __syncthreads();
    float2 r0 = red[px], r1 = red[64 + px], r2 = red[128 + px], r3 = red[192 + px];
    float st = r0.x + r1.x + r2.x + r3.x;
    float qt = r0.y + r1.y + r2.y + r3.y;
    const float invc = 1.f / CC;
    float mu = st * invc;
    float iv = rsqrtf(fmaxf(qt * invc - mu * mu, 0.f) + EPSLN);
    size_t base = ((size_t)b * CC + (size_t)cg * 48) * HWN + p;
    #pragma unroll
    for (int i = 0; i < 48; i++) {
        int c = cg * 48 + i;
        float o = (v[i] - mu) * iv * w[c] + bia[c];
        __nv_bfloat16 hb = __float2bfloat16_rn(o);
        Hi[base + (size_t)i * HWN] = __bfloat16_as_ushort(hb);
        __nv_bfloat16 lb = __float2bfloat16_rn(o - __bfloat162float(hb));
        Lo[base + (size_t)i * HWN] = __bfloat16_as_ushort(lb);
    }
}

// merged LN for x/kv1/kv2: grid (HWN/64, BB, 3)
__global__ __launch_bounds__(256)
void ln3(const float* __restrict__ X0, const float* __restrict__ X1, const float* __restrict__ X2,
         const float* __restrict__ w0, const float* __restrict__ b0,
         const float* __restrict__ w1, const float* __restrict__ b1,
         const float* __restrict__ w2, const float* __restrict__ b2) {
    int which = blockIdx.z;
    const float *X, *w, *bia;
    unsigned short *Hi, *Lo;
    if (which == 0)      { X = X0; w = w0; bia = b0; Hi = xt_a_hi;  Lo = xt_a_lo; }
    else if (which == 1) { X = X1; w = w1; bia = b1; Hi = xt_k1_hi; Lo = xt_k1_lo; }
    else                 { X = X2; w = w2; bia = b2; Hi = xt_k2_hi; Lo = xt_k2_lo; }
    ln_body(X, w, bia, Hi, Lo, blockIdx.y, blockIdx.x);
}

__global__ __launch_bounds__(256)
void ln_cp(const float* __restrict__ X, const float* __restrict__ w,
           const float* __restrict__ bia,
           unsigned short* __restrict__ Hi, unsigned short* __restrict__ Lo) {
    ln_body(X, w, bia, Hi, Lo, blockIdx.y, blockIdx.x);
}

// ---------------- depthwise 3x3 core over fp16 input ----------------
__device__ __forceinline__ void dw_core_h(const __half* __restrict__ xp, const float* kv,
                                          int h, int wcol, float& a0, float& a1,
                                          float& a2, float& a3) {
    #pragma unroll
    for (int dy = -1; dy <= 1; dy++) {
        int hh = h + dy;
        if (hh < 0 || hh >= HIMG) continue;
        const __half* r = xp + hh * HIMG + wcol;
        __half2 p01 = *(const __half2*)r;
        __half2 p23 = *(const __half2*)(r + 2);
        float m0 = __low2float(p01), m1 = __high2float(p01);
        float m2 = __low2float(p23), m3 = __high2float(p23);
        float lf = (wcol > 0) ? __half2float(r[-1]) : 0.f;
        float rt = (wcol < 124) ? __half2float(r[4]) : 0.f;
        const float* k = kv + (dy + 1) * 3;
        a0 += k[0]*lf + k[1]*m0 + k[2]*m1;
        a1 += k[0]*m0 + k[1]*m1 + k[2]*m2;
        a2 += k[0]*m1 + k[1]*m2 + k[2]*m3;
        a3 += k[0]*m2 + k[1]*m3 + k[2]*rt;
    }
}
__device__ __forceinline__ void st_half4(__half* dst, float a0, float a1, float a2, float a3) {
    __half2 h01 = __floats2half2_rn(a0, a1);
    __half2 h23 = __floats2half2_rn(a2, a3);
    uint2 u; u.x = *(unsigned*)&h01; u.y = *(unsigned*)&h23;
    *(uint2*)dst = u;
}

// merged kv1+kv2 depthwise (grid.y = 768)
__global__ void dwconv_kv(const float* __restrict__ Wt1, const float* __restrict__ Wt2) {
    int b = blockIdx.z, cc = blockIdx.y;
    int p = (blockIdx.x * 256 + threadIdx.x) * 4;
    int h = p >> 7, wcol = p & 127;
    const __half* X; const float* Wt; __half* Y; int c;
    if (cc < C2) { X = g_kv1pre; Wt = Wt1; Y = g_kv1; c = cc; }
    else         { X = g_kv2pre; Wt = Wt2; Y = g_kv2; c = cc - C2; }
    const __half* xp = X + ((size_t)b * C2 + c) * HWN;
    float kv[9];
    #pragma unroll
    for (int i = 0; i < 9; i++) kv[i] = Wt[(size_t)c * 9 + i];
    float a0 = 0, a1 = 0, a2 = 0, a3 = 0;
    dw_core_h(xp, kv, h, wcol, a0, a1, a2, a3);
    st_half4(Y + ((size_t)b * C2 + c) * HWN + p, a0, a1, a2, a3);
}

__global__ void dwconv_g2(const float* __restrict__ Wt) {
    int b = blockIdx.z, o = blockIdx.y;
    int p = (blockIdx.x * 256 + threadIdx.x) * 4;
    int h = p >> 7, wcol = p & 127;
    int i0 = (o >> 1) << 1;
    const __half* x0 = g_qpre + ((size_t)b * C2 + i0) * HWN;
    float kv[18];
    #pragma unroll
    for (int i = 0; i < 18; i++) kv[i] = Wt[(size_t)o * 18 + i];
    float a0 = 0, a1 = 0, a2 = 0, a3 = 0;
    dw_core_h(x0, kv, h, wcol, a0, a1, a2, a3);
    dw_core_h(x0 + HWN, kv + 9, h, wcol, a0, a1, a2, a3);
    st_half4(g_q + ((size_t)b * C2 + o) * HWN + p, a0, a1, a2, a3);
}

// ---------------- fused FFN dwconv + gated gelu -> bf16 [c][p] --------------
__global__ void dwgelu(const float* __restrict__ Wt,
                       unsigned short* __restrict__ Hi, unsigned short* __restrict__ Lo) {
    int b = blockIdx.z, c = blockIdx.y;
    int p = (blockIdx.x * 256 + threadIdx.x) * 4;
    size_t oidx = ((size_t)b * GGPAD + c) * HWN + p;
    if (c >= HIDC) {
        *(uint2*)(Hi + oidx) = make_uint2(0, 0);
        *(uint2*)(Lo + oidx) = make_uint2(0, 0);
        return;
    }
    int h = p >> 7, wcol = p & 127;
    float va[8];
    #pragma unroll
    for (int half = 0; half < 2; half++) {
        int ch = c + half * HIDC;
        const __half* xp = g_h + ((size_t)b * HID2 + ch) * HWN;
        float kv[9];
        #pragma unroll
        for (int i = 0; i < 9; i++) kv[i] = Wt[(size_t)ch * 9 + i];
        float a0 = 0, a1 = 0, a2 = 0, a3 = 0;
        dw_core_h(xp, kv, h, wcol, a0, a1, a2, a3);
        va[half*4+0] = a0; va[half*4+1] = a1; va[half*4+2] = a2; va[half*4+3] = a3;
    }
    float o[4];
    #pragma unroll
    for (int j = 0; j < 4; j++) {
        float a = va[j];
        float ge = 0.5f * a * (1.f + erff(a * 0.70710678118654752f));
        o[j] = ge * va[4+j];
    }
    unsigned h0, l0, h1, l1;
    cvt2(o[0], o[1], h0, l0);
    cvt2(o[2], o[3], h1, l1);
    *(uint2*)(Hi + oidx) = make_uint2(h0, h1);
    *(uint2*)(Lo + oidx) = make_uint2(l0, l1);
}

// ---------------- attention ----------------
__global__ void zero_attn() {
    int i = blockIdx.x * 256 + threadIdx.x;
    if (i < 32 * CHD * CHD) g_S[i] = 0.f;
    if (i < 32 * 96) g_nrm[i] = 0.f;
}

__global__ void skernel() {
    int m = blockIdx.x, ns = blockIdx.y;
    int b = m >> 3, br = (m >> 2) & 1, hh = m & 3;
    const __half* qb = g_q + ((size_t)b * C2 + br * CC + hh * CHD) * HWN;
    const __half* kb = (br ? g_kv2 : g_kv1) + ((size_t)b * C2 + hh * CHD) * HWN;
    __shared__ float Qs[CHD][65];
    __shared__ float Ks[CHD][65];
    int t = threadIdx.x;
    int tx = t & 15, ty = t >> 4;
    float acc[3][3];
    #pragma unroll
    for (int i = 0; i < 3; i++)
        #pragma unroll
        for (int j = 0; j < 3; j++) acc[i][j] = 0.f;
    const float* nrow = (t < CHD) ? &Qs[t][0] : ((t < 96) ? &Ks[t - CHD][0] : (const float*)0);
    float nacc = 0.f;
    int nbeg = ns * 1024;
    for (int n0 = nbeg; n0 < nbeg + 1024; n0 += 64) {
        #pragma unroll
        for (int i = t; i < CHD * 32; i += 256) {
            int rr = i >> 5, cc = (i & 31) * 2;
            __half2 qv2 = *(const __half2*)(qb + (size_t)rr * HWN + n0 + cc);
            __half2 kv2 = *(const __half2*)(kb + (size_t)rr * HWN + n0 + cc);
            Qs[rr][cc] = __low2float(qv2); Qs[rr][cc+1] = __high2float(qv2);
            Ks[rr][cc] = __low2float(kv2); Ks[rr][cc+1] = __high2float(kv2);
        }
        __syncthreads();
        if (nrow) {
            #pragma unroll 8
            for (int cc = 0; cc < 64; cc++) { float v = nrow[cc]; nacc += v * v; }
        }
        #pragma unroll 8
        for (int kk = 0; kk < 64; kk++) {
            float qv[3], kvv[3];
            #pragma unroll
            for (int i = 0; i < 3; i++) qv[i] = Qs[ty + 16 * i][kk];
            #pragma unroll
            for (int j = 0; j < 3; j++) kvv[j] = Ks[tx + 16 * j][kk];
            #pragma unroll
            for (int i = 0; i < 3; i++)
                #pragma unroll
                for (int j = 0; j < 3; j++) acc[i][j] += qv[i] * kvv[j];
        }
        __syncthreads();
    }
    #pragma unroll
    for (int i = 0; i < 3; i++)
        #pragma unroll
        for (int j = 0; j < 3; j++)
            atomicAdd(&g_S[m * CHD * CHD + (ty + 16 * i) * CHD + (tx + 16 * j)], acc[i][j]);
    if (t < 96) atomicAdd(&g_nrm[m * 96 + t], nacc);
}

__global__ void softmax_kernel(const float* __restrict__ t1, const float* __restrict__ t2) {
    int m = blockIdx.x;
    int c = threadIdx.x;
    __shared__ float nk[CHD];
    if (c < CHD) nk[c] = fmaxf(sqrtf(g_nrm[m * 96 + CHD + c]), 1e-12f);
    __syncthreads();
    if (c >= CHD) return;
    int br = (m >> 2) & 1, hh = m & 3;
    float tmp = (br ? t2 : t1)[hh];
    float nq = fmaxf(sqrtf(g_nrm[m * 96 + c]), 1e-12f);
    float* row = g_S + (size_t)m * CHD * CHD + c * CHD;
    float vals[CHD];
    float mx = -1e30f;
    #pragma unroll
    for (int d = 0; d < CHD; d++) {
        float v = row[d] / (nq * nk[d]) * tmp;
        vals[d] = v;
        mx = fmaxf(mx, v);
    }
    float sum = 0.f;
    #pragma unroll
    for (int d = 0; d < CHD; d++) { vals[d] = __expf(vals[d] - mx); sum += vals[d]; }
    float inv = 1.f / sum;
    #pragma unroll
    for (int d = 0; d < CHD; d++) row[d] = vals[d] * inv;
}

__global__ void av_cp() {
    int m = blockIdx.x;
    int b = m >> 3, br = (m >> 2) & 1, hh = m & 3;
    __shared__ float As[CHD * CHD];
    for (int i = threadIdx.x; i < CHD * CHD; i += 128) As[i] = g_S[(size_t)m * CHD * CHD + i];
    __syncthreads();
    const __half* vb = (br ? g_kv2 : g_kv1) + ((size_t)b * C2 + CC + hh * CHD) * HWN;
    int p = blockIdx.y * 256 + threadIdx.x * 2;
    float acc0[CHD], acc1[CHD];
    #pragma unroll
    for (int c = 0; c < CHD; c++) { acc0[c] = 0.f; acc1[c] = 0.f; }
    for (int d = 0; d < CHD; d++) {
        __half2 v2 = *(const __half2*)(vb + (size_t)d * HWN + p);
        float vx = __low2float(v2), vy = __high2float(v2);
        #pragma unroll
        for (int c = 0; c < CHD; c++) {
            float a = As[c * CHD + d];
            acc0[c] += a * vx;
            acc1[c] += a * vy;
        }
    }
    int off = br * CC + hh * CHD;
    size_t base = ((size_t)b * C2 + off) * HWN + p;
    #pragma unroll
    for (int c = 0; c < CHD; c++) {
        unsigned h, l; cvt2(acc0[c], acc1[c], h, l);
        *(unsigned*)(xt_ao_hi + base + (size_t)c * HWN) = h;
        *(unsigned*)(xt_ao_lo + base + (size_t)c * HWN) = l;
    }
}

// ---------------- launch ----------------
extern "C" void kernel_launch(void* const* d_in, const int* in_sizes, int n_in,
                              void* d_out, int out_size) {
    const float* x       = (const float*)d_in[0];
    const float* kv1in   = (const float*)d_in[1];
    const float* kv2in   = (const float*)d_in[2];
    const float* n1w = (const float*)d_in[3];  const float* n1b = (const float*)d_in[4];
    const float* nk1w = (const float*)d_in[5]; const float* nk1b = (const float*)d_in[6];
    const float* nk2w = (const float*)d_in[7]; const float* nk2b = (const float*)d_in[8];
    const float* n2w = (const float*)d_in[9];  const float* n2b = (const float*)d_in[10];
    const float* q_w   = (const float*)d_in[11];
    const float* kv1_w = (const float*)d_in[12];
    const float* kv2_w = (const float*)d_in[13];
    const float* q_dw  = (const float*)d_in[14];
    const float* kv1_dw= (const float*)d_in[15];
    const float* kv2_dw= (const float*)d_in[16];
    const float* proj_w= (const float*)d_in[17];
    const float* temp1 = (const float*)d_in[18];
    const float* temp2 = (const float*)d_in[19];
    const float* pin_w = (const float*)d_in[20];
    const float* dw_w  = (const float*)d_in[21];
    const float* pout_w= (const float*)d_in[22];
    float* out = (float*)d_out;

    cudaFuncSetAttribute((const void*)gemm_mma<false, true>,  cudaFuncAttributeMaxDynamicSharedMemorySize, GEMM_SMEM);
    cudaFuncSetAttribute((const void*)gemm_mma<true, false>,  cudaFuncAttributeMaxDynamicSharedMemorySize, GEMM_SMEM);
    cudaFuncSetAttribute((const void*)gemm3, cudaFuncAttributeMaxDynamicSharedMemorySize, GEMM_SMEM);

    float *p_x2;
    cudaGetSymbolAddress((void**)&p_x2, g_x2);
    __half *p_h;
    cudaGetSymbolAddress((void**)&p_h, g_h);
    unsigned short *whi, *wlo, *ahi, *alo, *aohi, *aolo, *gghi, *gglo;
    cudaGetSymbolAddress((void**)&whi, g_whi);
    cudaGetSymbolAddress((void**)&wlo, g_wlo);
    cudaGetSymbolAddress((void**)&ahi, xt_a_hi);
    cudaGetSymbolAddress((void**)&alo, xt_a_lo);
    cudaGetSymbolAddress((void**)&aohi, xt_ao_hi);
    cudaGetSymbolAddress((void**)&aolo, xt_ao_lo);
    cudaGetSymbolAddress((void**)&gghi, xt_gg_hi);
    cudaGetSymbolAddress((void**)&gglo, xt_gg_lo);

    // 1: weights
    wconv_all<<<2556, 64>>>(q_w, kv1_w, kv2_w, proj_w, pin_w, pout_w);
    // 2: merged LNs
    ln3<<<dim3(HWN / 64, BB, 3), 256>>>(x, kv1in, kv2in, n1w, n1b, nk1w, nk1b, nk2w, nk2b);
    // 3: zero attn accumulators
    zero_attn<<<300, 256>>>();
    // 4: merged q/kv1/kv2 GEMM (profiled slot)
    gemm3<<<dim3(HWN / 64, 3, 12), 256, GEMM_SMEM>>>();
    // 5-6: dwconvs
    dim3 dG(HWN / 1024, C2, BB);
    dwconv_g2<<<dG, 256>>>(q_dw);
    dim3 dKV(HWN / 1024, 2 * C2, BB);
    dwconv_kv<<<dKV, 256>>>(kv1_dw, kv2_dw);
    // 7-9: attention
    skernel<<<dim3(32, 16), 256>>>();
    softmax_kernel<<<32, 64>>>(temp1, temp2);
    av_cp<<<dim3(32, HWN / 256), 128>>>();
    // 10: proj + residual x -> g_x2 (fp32)
    dim3 gP(HWN / 64, 2, BB);
    gemm_mma<true, false><<<gP, 256, GEMM_SMEM>>>(whi + OFF_P, wlo + OFF_P, aohi, aolo, x, p_x2, 192, 384);
    // 11: FFN LN
    dim3 lnG(HWN / 64, BB);
    ln_cp<<<lnG, 256>>>(p_x2, n2w, n2b, ahi, alo);
    // 12: pin GEMM -> g_h (fp16)
    dim3 gIn(HWN / 64, 8, BB);
    gemm_mma<false, true><<<gIn, 256, GEMM_SMEM>>>(whi + OFF_PIN, wlo + OFF_PIN, ahi, alo, nullptr, p_h, 1020, 192);
    // 13: fused dwconv+gelu
    dim3 dGG(HWN / 1024, GGPAD, BB);
    dwgelu<<<dGG, 256>>>(dw_w, gghi, gglo);
    // 14: pout GEMM + residual
    gemm_mma<true, false><<<gP, 256, GEMM_SMEM>>>(whi + OFF_PO, wlo + OFF_PO, gghi, gglo, p_x2, out, 192, 512);
}

// round 10
// speedup vs baseline: 1.6951x; 1.4382x over previous
#include <cuda_runtime.h>
#include <cuda_fp16.h>
#include <math.h>

#define BB 4
#define CC 192
#define C2 384
#define HWN 16384
#define HIMG 128
#define CHD 48
#define HIDC 510
#define HID2 1020
#define GGPAD 512
#define EPSLN 1e-5f

__device__ __forceinline__ unsigned smem_u32(const void* p) {
    unsigned a;
    asm("{ .reg .u64 t; cvta.to.shared.u64 t, %1; cvt.u32.u64 %0, t; }"
        : "=r"(a) : "l"(p));
    return a;
}
#define CP_ASYNC16(dst, src) \
    asm volatile("cp.async.cg.shared.global [%0], [%1], 16;" :: "r"(dst), "l"(src))
#define CP_COMMIT() asm volatile("cp.async.commit_group;" ::: "memory")
#define CP_WAIT(n)  asm volatile("cp.async.wait_group %0;" :: "n"(n) : "memory")

__device__ __forceinline__ void ldm_x4(unsigned& r0, unsigned& r1, unsigned& r2, unsigned& r3,
                                       unsigned addr) {
    asm volatile("ldmatrix.sync.aligned.m8n8.x4.shared.b16 {%0,%1,%2,%3}, [%4];"
        : "=r"(r0), "=r"(r1), "=r"(r2), "=r"(r3) : "r"(addr));
}
__device__ __forceinline__ void ldm_x4_t(unsigned& r0, unsigned& r1, unsigned& r2, unsigned& r3,
                                         unsigned addr) {
    asm volatile("ldmatrix.sync.aligned.m8n8.x4.trans.shared.b16 {%0,%1,%2,%3}, [%4];"
        : "=r"(r0), "=r"(r1), "=r"(r2), "=r"(r3) : "r"(addr));
}
__device__ __forceinline__ void mma_f16(float* d, const unsigned* a, unsigned b0, unsigned b1) {
    asm volatile("mma.sync.aligned.m16n8k16.row.col.f32.f16.f16.f32 "
        "{%0,%1,%2,%3}, {%4,%5,%6,%7}, {%8,%9}, {%0,%1,%2,%3};"
        : "+f"(d[0]), "+f"(d[1]), "+f"(d[2]), "+f"(d[3])
        : "r"(a[0]), "r"(a[1]), "r"(a[2]), "r"(a[3]), "r"(b0), "r"(b1));
}

// ---------------- scratch ----------------
__device__ __align__(16) __half g_qpre [BB*C2*HWN];
__device__ __align__(16) __half g_kv1pre[BB*C2*HWN];
__device__ __align__(16) __half g_kv2pre[BB*C2*HWN];
__device__ __align__(16) __half g_q   [BB*C2*HWN];
__device__ __align__(16) __half g_kv1 [BB*C2*HWN];
__device__ __align__(16) __half g_kv2 [BB*C2*HWN];
__device__ __align__(16) __half g_h   [BB*HID2*HWN];
__device__ float g_x2  [BB*CC*HWN];
__device__ float g_S   [32*CHD*CHD];
__device__ float g_nrm [32*2*CHD];

// fp16 activations, natural layout: [b][channel][pixel]
__device__ __align__(16) __half xt_a [BB*CC*HWN];
__device__ __align__(16) __half xt_k1[BB*CC*HWN];
__device__ __align__(16) __half xt_k2[BB*CC*HWN];
__device__ __align__(16) __half xt_ao[BB*C2*HWN];
__device__ __align__(16) __half xt_gg[BB*GGPAD*HWN];
// converted weights (row-major [O][Cpad]), fp16
#define OFF_Q   0
#define OFF_K1  (384*192)
#define OFF_K2  (2*384*192)
#define OFF_P   (3*384*192)
#define OFF_PIN (3*384*192 + 192*384)
#define OFF_PO  (3*384*192 + 192*384 + 1020*192)
#define WTOT    (3*384*192 + 192*384 + 1020*192 + 192*512)
#define WPAD    (64*512)
__device__ __align__(16) __half g_wh[WTOT + WPAD];

// ---------------- fp32 -> fp16 helpers ----------------
__device__ __forceinline__ void st_half4(__half* dst, float a0, float a1, float a2, float a3) {
    __half2 h01 = __floats2half2_rn(a0, a1);
    __half2 h23 = __floats2half2_rn(a2, a3);
    uint2 u; u.x = *(unsigned*)&h01; u.y = *(unsigned*)&h23;
    *(uint2*)dst = u;
}

// ---------------- merged weight conversion (1 launch) ----------------
__global__ void wconv_all(const float* __restrict__ q_w, const float* __restrict__ kv1_w,
                          const float* __restrict__ kv2_w, const float* __restrict__ proj_w,
                          const float* __restrict__ pin_w, const float* __restrict__ pout_w) {
    int r = blockIdx.x;
    const float* W; int o, Cin, Cpad, off;
    if (r < 384)        { W = q_w;    o = r;        Cin = 192; Cpad = 192; off = OFF_Q; }
    else if (r < 768)   { W = kv1_w;  o = r - 384;  Cin = 192; Cpad = 192; off = OFF_K1; }
    else if (r < 1152)  { W = kv2_w;  o = r - 768;  Cin = 192; Cpad = 192; off = OFF_K2; }
    else if (r < 1344)  { W = proj_w; o = r - 1152; Cin = 384; Cpad = 384; off = OFF_P; }
    else if (r < 2364)  { W = pin_w;  o = r - 1344; Cin = 192; Cpad = 192; off = OFF_PIN; }
    else                { W = pout_w; o = r - 2364; Cin = 510; Cpad = 512; off = OFF_PO; }
    int c0 = threadIdx.x * 8;
    if (c0 >= Cpad) return;
    float v[8];
    #pragma unroll
    for (int j = 0; j < 8; j++) {
        int c = c0 + j;
        v[j] = (c < Cin) ? W[(size_t)o * Cin + c] : 0.f;
    }
    __half* dst = g_wh + (size_t)off + (size_t)o * Cpad + c0;
    st_half4(dst,     v[0], v[1], v[2], v[3]);
    st_half4(dst + 4, v[4], v[5], v[6], v[7]);
}

// ======================= HMMA GEMM body =====================================
// Y[b][o][p] = sum_c W[o][c] * X[b][c][p] (+ residual). Single fp16 HMMA.
#define BK 32
#define ASTRIDE 40
#define PSTR 72
#define A_BYTES (128 * ASTRIDE * 2)          // 10240
#define B_BYTES (BK * PSTR * 2)              // 4608
#define BUF_BYTES (A_BYTES + B_BYTES)        // 14848
#define GEMM_SMEM 34816                      // max(2*BUF, 128*YSTRIDE*4)
#define YSTRIDE 68

template<bool RESID, bool HALF_OUT>
__device__ __forceinline__
void gemm_body(const __half* __restrict__ W, const __half* __restrict__ XB,
               const float* __restrict__ R, void* __restrict__ Yv, int O, int Cpad,
               int b, int p0, int o0, char* dsm) {
    unsigned sbase = smem_u32(dsm);
    int t = threadIdx.x, wid = t >> 5, lane = t & 31;
    int warpM = (wid >> 1) * 32;
    int warpN = (wid & 1) * 32;

    const __half* WB = W + (size_t)o0 * Cpad;

    int nk = Cpad / BK;

    auto fill = [&](int kt) {
        int buf = kt & 1;
        unsigned bb = sbase + buf * BUF_BYTES;
        int k0 = kt * BK;
        #pragma unroll
        for (int j = 0; j < 3; j++) {
            int ci = j * 256 + t;
            if (ci < 512) {
                int row = ci >> 2, g = ci & 3;
                const __half* src = WB + (size_t)row * Cpad + k0 + g * 8;
                unsigned dst = bb + (unsigned)(row * ASTRIDE + g * 8) * 2;
                CP_ASYNC16(dst, src);
            } else {
                int m = ci - 512;
                int row = m >> 3, g = m & 7;
                const __half* src = XB + (size_t)(k0 + row) * HWN + g * 8;
                unsigned dst = bb + A_BYTES + (unsigned)(row * PSTR + g * 8) * 2;
                CP_ASYNC16(dst, src);
            }
        }
        CP_COMMIT();
    };

    float acc[2][4][4];
    #pragma unroll
    for (int i = 0; i < 2; i++)
        #pragma unroll
        for (int j = 0; j < 4; j++)
            #pragma unroll
            for (int k = 0; k < 4; k++) acc[i][j][k] = 0.f;

    fill(0);

    int rsel = lane & 15, csel = (lane >> 4) * 8;
    int bkr = (lane & 7) + ((lane >> 4) & 1) * 8;
    int bpc = ((lane >> 3) & 1) * 8;

    for (int kt = 0; kt < nk; kt++) {
        if (kt + 1 < nk) { fill(kt + 1); CP_WAIT(1); }
        else             { CP_WAIT(0); }
        __syncthreads();

        unsigned bb = sbase + (kt & 1) * BUF_BYTES;
        unsigned Aa = bb, Ba = bb + A_BYTES;

        #pragma unroll
        for (int kk = 0; kk < 2; kk++) {
            int kc = csel + kk * 16;
            unsigned af[2][4], bf[2][4];
            #pragma unroll
            for (int mt = 0; mt < 2; mt++) {
                unsigned off = (unsigned)((warpM + mt * 16 + rsel) * ASTRIDE + kc) * 2;
                ldm_x4(af[mt][0], af[mt][1], af[mt][2], af[mt][3], Aa + off);
            }
            #pragma unroll
            for (int np = 0; np < 2; np++) {
                unsigned off = (unsigned)((kk * 16 + bkr) * PSTR + warpN + np * 16 + bpc) * 2;
                ldm_x4_t(bf[np][0], bf[np][1], bf[np][2], bf[np][3], Ba + off);
            }
            #pragma unroll
            for (int mt = 0; mt < 2; mt++)
                #pragma unroll
                for (int nt = 0; nt < 4; nt++) {
                    int np = nt >> 1, hf = nt & 1;
                    mma_f16(acc[mt][nt], af[mt], bf[np][hf], bf[np][hf + 2]);
                }
        }
        __syncthreads();
    }

    float* Ysm = (float*)dsm;
    #pragma unroll
    for (int mt = 0; mt < 2; mt++)
        #pragma unroll
        for (int nt = 0; nt < 4; nt++) {
            int r0 = warpM + mt * 16 + (lane >> 2);
            int cc = warpN + nt * 8 + (lane & 3) * 2;
            Ysm[r0 * YSTRIDE + cc]           = acc[mt][nt][0];
            Ysm[r0 * YSTRIDE + cc + 1]       = acc[mt][nt][1];
            Ysm[(r0 + 8) * YSTRIDE + cc]     = acc[mt][nt][2];
            Ysm[(r0 + 8) * YSTRIDE + cc + 1] = acc[mt][nt][3];
        }
    __syncthreads();
    #pragma unroll
    for (int i = 0; i < 8; i++) {
        int idx = i * 256 + t;
        int row = idx >> 4, c4 = (idx & 15) * 4;
        int o = o0 + row;
        if (o < O) {
            float4 v = *(float4*)(Ysm + row * YSTRIDE + c4);
            size_t goff = ((size_t)b * O + o) * HWN + p0 + c4;
            if (HALF_OUT) {
                st_half4((__half*)Yv + goff, v.x, v.y, v.z, v.w);
            } else {
                if (RESID) {
                    float4 q = *(const float4*)(R + goff);
                    v.x += q.x; v.y += q.y; v.z += q.z; v.w += q.w;
                }
                *(float4*)((float*)Yv + goff) = v;
            }
        }
    }
}

template<bool RESID, bool HALF_OUT>
__global__ __launch_bounds__(256)
void gemm_mma(const __half* __restrict__ W, const __half* __restrict__ X,
              const float* __restrict__ R, void* __restrict__ Y, int O, int Cpad) {
    extern __shared__ char dsm[];
    int b = blockIdx.z;
    gemm_body<RESID, HALF_OUT>(W,
                     X + (size_t)b * Cpad * HWN + blockIdx.x * 64,
                     R, Y, O, Cpad, b, blockIdx.x * 64, blockIdx.y * 128, dsm);
}

// merged q/kv1/kv2 GEMM: grid (256, 3, 12); z: which = z>>2, b = z&3
__global__ __launch_bounds__(256)
void gemm3(void) {
    extern __shared__ char dsm[];
    int z = blockIdx.z, which = z >> 2, b = z & 3;
    const __half *W, *X;
    __half* Y;
    if (which == 0)      { W = g_wh + OFF_Q;  X = xt_a;  Y = g_qpre; }
    else if (which == 1) { W = g_wh + OFF_K1; X = xt_k1; Y = g_kv1pre; }
    else                 { W = g_wh + OFF_K2; X = xt_k2; Y = g_kv2pre; }
    gemm_body<false, true>(W,
                     X + (size_t)b * CC * HWN + blockIdx.x * 64,
                     nullptr, Y, C2, CC, b, blockIdx.x * 64, blockIdx.y * 128, dsm);
}

// ---------------- LayerNorm -> fp16 [c][p] ----------------------------------
// block = 256 threads = 64 pixels x 4 channel-groups (48 ch each).
__device__ __forceinline__
void ln_body(const float* __restrict__ X, const float* __restrict__ w,
             const float* __restrict__ bia, __half* __restrict__ Hx,
             int b, int pblk) {
    __shared__ float2 red[256];
    int px = threadIdx.x & 63, cg = threadIdx.x >> 6;
    int p = pblk * 64 + px;
    const float* xp = X + ((size_t)b * CC + (size_t)cg * 48) * HWN + p;
    float v[48];
    float s = 0.f, q = 0.f;
    #pragma unroll
    for (int i = 0; i < 48; i++) {
        float t = xp[(size_t)i * HWN];
        v[i] = t; s += t; q += t * t;
    }
    red[threadIdx.x] = make_float2(s, q);
    __syncthreads();
    float2 r0 = red[px], r1 = red[64 + px], r2 = red[128 + px], r3 = red[192 + px];
    float st = r0.x + r1.x + r2.x + r3.x;
    float qt = r0.y + r1.y + r2.y + r3.y;
    const float invc = 1.f / CC;
    float mu = st * invc;
    float iv = rsqrtf(fmaxf(qt * invc - mu * mu, 0.f) + EPSLN);
    size_t base = ((size_t)b * CC + (size_t)cg * 48) * HWN + p;
    #pragma unroll
    for (int i = 0; i < 48; i++) {
        int c = cg * 48 + i;
        float o = (v[i] - mu) * iv * w[c] + bia[c];
        Hx[base + (size_t)i * HWN] = __float2half_rn(o);
    }
}

// merged LN for x/kv1/kv2: grid (HWN/64, BB, 3)
__global__ __launch_bounds__(256)
void ln3(const float* __restrict__ X0, const float* __restrict__ X1, const float* __restrict__ X2,
         const float* __restrict__ w0, const float* __restrict__ b0,
         const float* __restrict__ w1, const float* __restrict__ b1,
         const float* __restrict__ w2, const float* __restrict__ b2) {
    int which = blockIdx.z;
    const float *X, *w, *bia;
    __half* Hx;
    if (which == 0)      { X = X0; w = w0; bia = b0; Hx = xt_a; }
    else if (which == 1) { X = X1; w = w1; bia = b1; Hx = xt_k1; }
    else                 { X = X2; w = w2; bia = b2; Hx = xt_k2; }
    ln_body(X, w, bia, Hx, blockIdx.y, blockIdx.x);
}

__global__ __launch_bounds__(256)
void ln_cp(const float* __restrict__ X, const float* __restrict__ w,
           const float* __restrict__ bia, __half* __restrict__ Hx) {
    ln_body(X, w, bia, Hx, blockIdx.y, blockIdx.x);
}

// ---------------- depthwise 3x3 core over fp16 input ----------------
__device__ __forceinline__ void dw_core_h(const __half* __restrict__ xp, const float* kv,
                                          int h, int wcol, float& a0, float& a1,
                                          float& a2, float& a3) {
    #pragma unroll
    for (int dy = -1; dy <= 1; dy++) {
        int hh = h + dy;
        if (hh < 0 || hh >= HIMG) continue;
        const __half* r = xp + hh * HIMG + wcol;
        __half2 p01 = *(const __half2*)r;
        __half2 p23 = *(const __half2*)(r + 2);
        float m0 = __low2float(p01), m1 = __high2float(p01);
        float m2 = __low2float(p23), m3 = __high2float(p23);
        float lf = (wcol > 0) ? __half2float(r[-1]) : 0.f;
        float rt = (wcol < 124) ? __half2float(r[4]) : 0.f;
        const float* k = kv + (dy + 1) * 3;
        a0 += k[0]*lf + k[1]*m0 + k[2]*m1;
        a1 += k[0]*m0 + k[1]*m1 + k[2]*m2;
        a2 += k[0]*m1 + k[1]*m2 + k[2]*m3;
        a3 += k[0]*m2 + k[1]*m3 + k[2]*rt;
    }
}

// merged kv1+kv2 depthwise (grid.y = 768)
__global__ void dwconv_kv(const float* __restrict__ Wt1, const float* __restrict__ Wt2) {
    int b = blockIdx.z, cc = blockIdx.y;
    int p = (blockIdx.x * 256 + threadIdx.x) * 4;
    int h = p >> 7, wcol = p & 127;
    const __half* X; const float* Wt; __half* Y; int c;
    if (cc < C2) { X = g_kv1pre; Wt = Wt1; Y = g_kv1; c = cc; }
    else         { X = g_kv2pre; Wt = Wt2; Y = g_kv2; c = cc - C2; }
    const __half* xp = X + ((size_t)b * C2 + c) * HWN;
    float kv[9];
    #pragma unroll
    for (int i = 0; i < 9; i++) kv[i] = Wt[(size_t)c * 9 + i];
    float a0 = 0, a1 = 0, a2 = 0, a3 = 0;
    dw_core_h(xp, kv, h, wcol, a0, a1, a2, a3);
    st_half4(Y + ((size_t)b * C2 + c) * HWN + p, a0, a1, a2, a3);
}

__global__ void dwconv_g2(const float* __restrict__ Wt) {
    int b = blockIdx.z, o = blockIdx.y;
    int p = (blockIdx.x * 256 + threadIdx.x) * 4;
    int h = p >> 7, wcol = p & 127;
    int i0 = (o >> 1) << 1;
    const __half* x0 = g_qpre + ((size_t)b * C2 + i0) * HWN;
    float kv[18];
    #pragma unroll
    for (int i = 0; i < 18; i++) kv[i] = Wt[(size_t)o * 18 + i];
    float a0 = 0, a1 = 0, a2 = 0, a3 = 0;
    dw_core_h(x0, kv, h, wcol, a0, a1, a2, a3);
    dw_core_h(x0 + HWN, kv + 9, h, wcol, a0, a1, a2, a3);
    st_half4(g_q + ((size_t)b * C2 + o) * HWN + p, a0, a1, a2, a3);
}

// ---------------- fused FFN dwconv + gated gelu -> fp16 [c][p] --------------
__global__ void dwgelu(const float* __restrict__ Wt, __half* __restrict__ Hx) {
    int b = blockIdx.z, c = blockIdx.y;
    int p = (blockIdx.x * 256 + threadIdx.x) * 4;
    size_t oidx = ((size_t)b * GGPAD + c) * HWN + p;
    if (c >= HIDC) {
        *(uint2*)(Hx + oidx) = make_uint2(0, 0);
        return;
    }
    int h = p >> 7, wcol = p & 127;
    float va[8];
    #pragma unroll
    for (int half = 0; half < 2; half++) {
        int ch = c + half * HIDC;
        const __half* xp = g_h + ((size_t)b * HID2 + ch) * HWN;
        float kv[9];
        #pragma unroll
        for (int i = 0; i < 9; i++) kv[i] = Wt[(size_t)ch * 9 + i];
        float a0 = 0, a1 = 0, a2 = 0, a3 = 0;
        dw_core_h(xp, kv, h, wcol, a0, a1, a2, a3);
        va[half*4+0] = a0; va[half*4+1] = a1; va[half*4+2] = a2; va[half*4+3] = a3;
    }
    float o[4];
    #pragma unroll
    for (int j = 0; j < 4; j++) {
        float a = va[j];
        float ge = 0.5f * a * (1.f + erff(a * 0.70710678118654752f));
        o[j] = ge * va[4+j];
    }
    st_half4(Hx + oidx, o[0], o[1], o[2], o[3]);
}

// ---------------- attention ----------------
__global__ void zero_attn() {
    int i = blockIdx.x * 256 + threadIdx.x;
    if (i < 32 * CHD * CHD) g_S[i] = 0.f;
    if (i < 32 * 96) g_nrm[i] = 0.f;
}

__global__ void skernel() {
    int m = blockIdx.x, ns = blockIdx.y;
    int b = m >> 3, br = (m >> 2) & 1, hh = m & 3;
    const __half* qb = g_q + ((size_t)b * C2 + br * CC + hh * CHD) * HWN;
    const __half* kb = (br ? g_kv2 : g_kv1) + ((size_t)b * C2 + hh * CHD) * HWN;
    __shared__ float Qs[CHD][65];
    __shared__ float Ks[CHD][65];
    int t = threadIdx.x;
    int tx = t & 15, ty = t >> 4;
    float acc[3][3];
    #pragma unroll
    for (int i = 0; i < 3; i++)
        #pragma unroll
        for (int j = 0; j < 3; j++) acc[i][j] = 0.f;
    const float* nrow = (t < CHD) ? &Qs[t][0] : ((t < 96) ? &Ks[t - CHD][0] : (const float*)0);
    float nacc = 0.f;
    int nbeg = ns * 1024;
    for (int n0 = nbeg; n0 < nbeg + 1024; n0 += 64) {
        #pragma unroll
        for (int i = t; i < CHD * 32; i += 256) {
            int rr = i >> 5, cc = (i & 31) * 2;
            __half2 qv2 = *(const __half2*)(qb + (size_t)rr * HWN + n0 + cc);
            __half2 kv2 = *(const __half2*)(kb + (size_t)rr * HWN + n0 + cc);
            Qs[rr][cc] = __low2float(qv2); Qs[rr][cc+1] = __high2float(qv2);
            Ks[rr][cc] = __low2float(kv2); Ks[rr][cc+1] = __high2float(kv2);
        }
        __syncthreads();
        if (nrow) {
            #pragma unroll 8
            for (int cc = 0; cc < 64; cc++) { float v = nrow[cc]; nacc += v * v; }
        }
        #pragma unroll 8
        for (int kk = 0; kk < 64; kk++) {
            float qv[3], kvv[3];
            #pragma unroll
            for (int i = 0; i < 3; i++) qv[i] = Qs[ty + 16 * i][kk];
            #pragma unroll
            for (int j = 0; j < 3; j++) kvv[j] = Ks[tx + 16 * j][kk];
            #pragma unroll
            for (int i = 0; i < 3; i++)
                #pragma unroll
                for (int j = 0; j < 3; j++) acc[i][j] += qv[i] * kvv[j];
        }
        __syncthreads();
    }
    #pragma unroll
    for (int i = 0; i < 3; i++)
        #pragma unroll
        for (int j = 0; j < 3; j++)
            atomicAdd(&g_S[m * CHD * CHD + (ty + 16 * i) * CHD + (tx + 16 * j)], acc[i][j]);
    if (t < 96) atomicAdd(&g_nrm[m * 96 + t], nacc);
}

__global__ void softmax_kernel(const float* __restrict__ t1, const float* __restrict__ t2) {
    int m = blockIdx.x;
    int c = threadIdx.x;
    __shared__ float nk[CHD];
    if (c < CHD) nk[c] = fmaxf(sqrtf(g_nrm[m * 96 + CHD + c]), 1e-12f);
    __syncthreads();
    if (c >= CHD) return;
    int br = (m >> 2) & 1, hh = m & 3;
    float tmp = (br ? t2 : t1)[hh];
    float nq = fmaxf(sqrtf(g_nrm[m * 96 + c]), 1e-12f);
    float* row = g_S + (size_t)m * CHD * CHD + c * CHD;
    float vals[CHD];
    float mx = -1e30f;
    #pragma unroll
    for (int d = 0; d < CHD; d++) {
        float v = row[d] / (nq * nk[d]) * tmp;
        vals[d] = v;
        mx = fmaxf(mx, v);
    }
    float sum = 0.f;
    #pragma unroll
    for (int d = 0; d < CHD; d++) { vals[d] = __expf(vals[d] - mx); sum += vals[d]; }
    float inv = 1.f / sum;
    #pragma unroll
    for (int d = 0; d < CHD; d++) row[d] = vals[d] * inv;
}

__global__ void av_cp() {
    int m = blockIdx.x;
    int b = m >> 3, br = (m >> 2) & 1, hh = m & 3;
    __shared__ float As[CHD * CHD];
    for (int i = threadIdx.x; i < CHD * CHD; i += 128) As[i] = g_S[(size_t)m * CHD * CHD + i];
    __syncthreads();
    const __half* vb = (br ? g_kv2 : g_kv1) + ((size_t)b * C2 + CC + hh * CHD) * HWN;
    int p = blockIdx.y * 256 + threadIdx.x * 2;
    float acc0[CHD], acc1[CHD];
    #pragma unroll
    for (int c = 0; c < CHD; c++) { acc0[c] = 0.f; acc1[c] = 0.f; }
    for (int d = 0; d < CHD; d++) {
        __half2 v2 = *(const __half2*)(vb + (size_t)d * HWN + p);
        float vx = __low2float(v2), vy = __high2float(v2);
        #pragma unroll
        for (int c = 0; c < CHD; c++) {
            float a = As[c * CHD + d];
            acc0[c] += a * vx;
            acc1[c] += a * vy;
        }
    }
    int off = br * CC + hh * CHD;
    size_t base = ((size_t)b * C2 + off) * HWN + p;
    #pragma unroll
    for (int c = 0; c < CHD; c++) {
        __half2 h2 = __floats2half2_rn(acc0[c], acc1[c]);
        *(__half2*)(xt_ao + base + (size_t)c * HWN) = h2;
    }
}

// ---------------- launch ----------------
extern "C" void kernel_launch(void* const* d_in, const int* in_sizes, int n_in,
                              void* d_out, int out_size) {
    const float* x       = (const float*)d_in[0];
    const float* kv1in   = (const float*)d_in[1];
    const float* kv2in   = (const float*)d_in[2];
    const float* n1w = (const float*)d_in[3];  const float* n1b = (const float*)d_in[4];
    const float* nk1w = (const float*)d_in[5]; const float* nk1b = (const float*)d_in[6];
    const float* nk2w = (const float*)d_in[7]; const float* nk2b = (const float*)d_in[8];
    const float* n2w = (const float*)d_in[9];  const float* n2b = (const float*)d_in[10];
    const float* q_w   = (const float*)d_in[11];
    const float* kv1_w = (const float*)d_in[12];
    const float* kv2_w = (const float*)d_in[13];
    const float* q_dw  = (const float*)d_in[14];
    const float* kv1_dw= (const float*)d_in[15];
    const float* kv2_dw= (const float*)d_in[16];
    const float* proj_w= (const float*)d_in[17];
    const float* temp1 = (const float*)d_in[18];
    const float* temp2 = (const float*)d_in[19];
    const float* pin_w = (const float*)d_in[20];
    const float* dw_w  = (const float*)d_in[21];
    const float* pout_w= (const float*)d_in[22];
    float* out = (float*)d_out;

    cudaFuncSetAttribute((const void*)gemm_mma<false, true>,  cudaFuncAttributeMaxDynamicSharedMemorySize, GEMM_SMEM);
    cudaFuncSetAttribute((const void*)gemm_mma<true, false>,  cudaFuncAttributeMaxDynamicSharedMemorySize, GEMM_SMEM);
    cudaFuncSetAttribute((const void*)gemm3, cudaFuncAttributeMaxDynamicSharedMemorySize, GEMM_SMEM);

    float *p_x2;
    cudaGetSymbolAddress((void**)&p_x2, g_x2);
    __half *p_h, *wh, *pa, *pao, *pgg;
    cudaGetSymbolAddress((void**)&p_h, g_h);
    cudaGetSymbolAddress((void**)&wh, g_wh);
    cudaGetSymbolAddress((void**)&pa, xt_a);
    cudaGetSymbolAddress((void**)&pao, xt_ao);
    cudaGetSymbolAddress((void**)&pgg, xt_gg);

    // 1: weights
    wconv_all<<<2556, 64>>>(q_w, kv1_w, kv2_w, proj_w, pin_w, pout_w);
    // 2: merged LNs
    ln3<<<dim3(HWN / 64, BB, 3), 256>>>(x, kv1in, kv2in, n1w, n1b, nk1w, nk1b, nk2w, nk2b);
    // 3: zero attn accumulators
    zero_attn<<<300, 256>>>();
    // 4: merged q/kv1/kv2 GEMM (profiled slot)
    gemm3<<<dim3(HWN / 64, 3, 12), 256, GEMM_SMEM>>>();
    // 5-6: dwconvs
    dim3 dG(HWN / 1024, C2, BB);
    dwconv_g2<<<dG, 256>>>(q_dw);
    dim3 dKV(HWN / 1024, 2 * C2, BB);
    dwconv_kv<<<dKV, 256>>>(kv1_dw, kv2_dw);
    // 7-9: attention
    skernel<<<dim3(32, 16), 256>>>();
    softmax_kernel<<<32, 64>>>(temp1, temp2);
    av_cp<<<dim3(32, HWN / 256), 128>>>();
    // 10: proj + residual x -> g_x2 (fp32)
    dim3 gP(HWN / 64, 2, BB);
    gemm_mma<true, false><<<gP, 256, GEMM_SMEM>>>(wh + OFF_P, pao, x, p_x2, 192, 384);
    // 11: FFN LN
    dim3 lnG(HWN / 64, BB);
    ln_cp<<<lnG, 256>>>(p_x2, n2w, n2b, pa);
    // 12: pin GEMM -> g_h (fp16)
    dim3 gIn(HWN / 64, 8, BB);
    gemm_mma<false, true><<<gIn, 256, GEMM_SMEM>>>(wh + OFF_PIN, pa, nullptr, p_h, 1020, 192);
    // 13: fused dwconv+gelu
    dim3 dGG(HWN / 1024, GGPAD, BB);
    dwgelu<<<dGG, 256>>>(dw_w, pgg);
    // 14: pout GEMM + residual
    gemm_mma<true, false><<<gP, 256, GEMM_SMEM>>>(wh + OFF_PO, pgg, p_x2, out, 192, 512);
}